// round 13
// baseline (speedup 1.0000x reference)
#include <cuda_runtime.h>
#include <stdint.h>
#include <math.h>

#define NMAX 50000
#define EPS_LN 1e-5f
#define EPW 16

typedef unsigned long long u64;

// Scratch: P = x @ sp_w1[0:64,:] + sp_b1, Q = x @ sp_w1[64:128,:]   (each [N,256])
__device__ float g_P[(size_t)NMAX * 256];
__device__ float g_Q[(size_t)NMAX * 256];

// ---------------- f32x2 packed helpers ----------------
__device__ __forceinline__ u64 f2pack(float lo, float hi) {
    u64 r; asm("mov.b64 %0, {%1, %2};" : "=l"(r) : "f"(lo), "f"(hi)); return r;
}
__device__ __forceinline__ void f2unpack(u64 v, float& lo, float& hi) {
    asm("mov.b64 {%0, %1}, %2;" : "=f"(lo), "=f"(hi) : "l"(v));
}
__device__ __forceinline__ u64 dup2(float v) { return f2pack(v, v); }
__device__ __forceinline__ u64 fma2(u64 a, u64 b, u64 c) {
    u64 d; asm("fma.rn.f32x2 %0, %1, %2, %3;" : "=l"(d) : "l"(a), "l"(b), "l"(c)); return d;
}
__device__ __forceinline__ u64 add2(u64 a, u64 b) {
    u64 d; asm("add.rn.f32x2 %0, %1, %2;" : "=l"(d) : "l"(a), "l"(b)); return d;
}
__device__ __forceinline__ u64 mul2(u64 a, u64 b) {
    u64 d; asm("mul.rn.f32x2 %0, %1, %2;" : "=l"(d) : "l"(a), "l"(b)); return d;
}
__device__ __forceinline__ float rcp_fast(float x) {
    float r; asm("rcp.approx.f32 %0, %1;" : "=f"(r) : "f"(x)); return r;
}
__device__ __forceinline__ float ex2_fast(float x) {
    float r; asm("ex2.approx.f32 %0, %1;" : "=f"(r) : "f"(x)); return r;
}

__device__ __forceinline__ float wredsum(float v) {
#pragma unroll
    for (int o = 16; o > 0; o >>= 1) v += __shfl_xor_sync(0xffffffffu, v, o);
    return v;
}
__device__ __forceinline__ void wredsum2(float& a, float& b) {
#pragma unroll
    for (int o = 16; o > 0; o >>= 1) {
        float ta = __shfl_xor_sync(0xffffffffu, a, o);
        float tb = __shfl_xor_sync(0xffffffffu, b, o);
        a += ta;
        b += tb;
    }
}

// fast GELU via Hastings 3-term erf (A&S 7.1.25, |err| <= 2.5e-5)
__device__ __forceinline__ float gelu_fast(float u) {
    float z = 0.70710678118654752f * u;
    float az = fabsf(z);
    float t = rcp_fast(fmaf(0.47047f, az, 1.0f));
    float poly = t * fmaf(t, fmaf(t, 0.7478556f, -0.0958798f), 0.3480242f);
    float e = ex2_fast(-az * az * 1.4426950408889634f);
    float erf_z = copysignf(fmaf(-poly, e, 1.0f), z);
    return 0.5f * u * (1.0f + erf_z);
}

// ============================================================================
// K1: P,Q = x @ W_top (+b1), x @ W_bot.  32-node tile, 256 threads, scalar.
// ============================================================================
__global__ __launch_bounds__(256) void k_pq(const float* __restrict__ x,
                                            const float* __restrict__ w,   // [128,256]
                                            const float* __restrict__ b1,  // [256]
                                            int N) {
    __shared__ float xs[32][64];
    const int t = threadIdx.x;
    const int n0 = blockIdx.x * 32;

    {
        float4* xs4 = reinterpret_cast<float4*>(&xs[0][0]);
        const float4* x4 = reinterpret_cast<const float4*>(x);
#pragma unroll
        for (int i = t; i < 512; i += 256) {
            int node = n0 + (i >> 4);
            float4 v = make_float4(0.f, 0.f, 0.f, 0.f);
            if (node < N) v = x4[(size_t)node * 16 + (i & 15)];
            xs4[i] = v;
        }
    }
    __syncthreads();

    float aP[32], aQ[32];
#pragma unroll
    for (int m = 0; m < 32; m++) { aP[m] = 0.f; aQ[m] = 0.f; }

    const int c = t;
#pragma unroll 2
    for (int k4 = 0; k4 < 16; k4++) {
        float wp[4], wq[4];
#pragma unroll
        for (int j = 0; j < 4; j++) {
            int k = k4 * 4 + j;
            wp[j] = w[k * 256 + c];
            wq[j] = w[(64 + k) * 256 + c];
        }
#pragma unroll
        for (int m = 0; m < 32; m++) {
            float4 xv = *reinterpret_cast<const float4*>(&xs[m][k4 * 4]);
            float xa[4] = {xv.x, xv.y, xv.z, xv.w};
#pragma unroll
            for (int j = 0; j < 4; j++) {
                aP[m] = fmaf(xa[j], wp[j], aP[m]);
                aQ[m] = fmaf(xa[j], wq[j], aQ[m]);
            }
        }
    }

    const float bb = b1[c];
#pragma unroll
    for (int m = 0; m < 32; m++) {
        int n = n0 + m;
        if (n >= N) break;
        g_P[(size_t)n * 256 + c] = aP[m] + bb;
        g_Q[(size_t)n * 256 + c] = aQ[m];
    }
}

// ============================================================================
// Edge role: out = GELU(LN(P[row]+Q[col])) . w2 + b2
// Single-edge, f32x2; per-lane packed params live in SMEM [param][lane]
// (frees ~24 regs -> fits 64-reg ceiling for occupancy 8).
// ============================================================================
__device__ __forceinline__ void edge_role(int eb, char* smem_raw,
                                          const int* __restrict__ ei, int E,
                                          const float* __restrict__ gm,
                                          const float* __restrict__ bt,
                                          const float* __restrict__ w2,
                                          const float* __restrict__ b2p,
                                          float* __restrict__ out) {
    const int t = threadIdx.x;
    const int lane = t & 31;
    const int wid = t >> 5;

    // params in smem: [12][32] u64  (g2[0..3], be2[0..3], hw2[0..3])
    u64 (*prm)[32] = reinterpret_cast<u64 (*)[32]>(smem_raw);
    if (t < 32) {
        const float4* gmv = reinterpret_cast<const float4*>(gm);
        const float4* btv = reinterpret_cast<const float4*>(bt);
        const float4* w2v = reinterpret_cast<const float4*>(w2);
        float4 rga = gmv[t], rgb = gmv[32 + t];
        float4 rba = btv[t], rbb = btv[32 + t];
        float4 rwa = w2v[t], rwb = w2v[32 + t];
        const float RS2 = 0.70710678118654752f;
        prm[0][t] = f2pack(rga.x * RS2, rga.y * RS2);
        prm[1][t] = f2pack(rga.z * RS2, rga.w * RS2);
        prm[2][t] = f2pack(rgb.x * RS2, rgb.y * RS2);
        prm[3][t] = f2pack(rgb.z * RS2, rgb.w * RS2);
        prm[4][t] = f2pack(rba.x * RS2, rba.y * RS2);
        prm[5][t] = f2pack(rba.z * RS2, rba.w * RS2);
        prm[6][t] = f2pack(rbb.x * RS2, rbb.y * RS2);
        prm[7][t] = f2pack(rbb.z * RS2, rbb.w * RS2);
        prm[8][t] = f2pack(rwa.x * RS2, rwa.y * RS2);
        prm[9][t] = f2pack(rwa.z * RS2, rwa.w * RS2);
        prm[10][t] = f2pack(rwb.x * RS2, rwb.y * RS2);
        prm[11][t] = f2pack(rwb.z * RS2, rwb.w * RS2);
    }
    __syncthreads();

    long e0 = ((long)eb * 4 + wid) * EPW;
    if (e0 >= E) return;
    const int nE = (int)(E - e0 < EPW ? E - e0 : EPW);

    const u64 ONE2 = dup2(1.0f);
    const u64 PC = dup2(0.47047f);
    const u64 C3 = dup2(-0.7478556f);
    const u64 C2C = dup2(0.0958798f);
    const u64 C1 = dup2(-0.3480242f);
    const u64 NL2E = dup2(-1.4426950408889634f);
    const u64 AMASK = 0x7FFFFFFF7FFFFFFFull;
    const u64 SMASK = 0x8000000080000000ull;

    const float b2 = __ldg(b2p);

    const ulonglong2* P2v = reinterpret_cast<const ulonglong2*>(g_P);
    const ulonglong2* Q2v = reinterpret_cast<const ulonglong2*>(g_Q);

    // vectorized index load: lanes 0-15 row idx, lanes 16-31 col idx
    const int li = lane & 15;
    int idx = 0;
    if (li < nE) idx = ei[(lane < 16 ? e0 + li : (long)E + e0 + li)];

    for (int i = 0; i < nE; i++) {
        int r = __shfl_sync(0xffffffffu, idx, i);
        int c = __shfl_sync(0xffffffffu, idx, 16 + i);

        ulonglong2 pa = P2v[(size_t)r * 64 + lane];
        ulonglong2 pb = P2v[(size_t)r * 64 + 32 + lane];
        ulonglong2 qa = Q2v[(size_t)c * 64 + lane];
        ulonglong2 qb = Q2v[(size_t)c * 64 + 32 + lane];

        u64 s0 = add2(pa.x, qa.x), s1 = add2(pa.y, qa.y);
        u64 s2 = add2(pb.x, qb.x), s3 = add2(pb.y, qb.y);

        u64 sum2 = add2(add2(s0, s1), add2(s2, s3));
        u64 sq2 = fma2(s0, s0, fma2(s1, s1, fma2(s2, s2, mul2(s3, s3))));
        float slo, shi, sqlo, sqhi;
        f2unpack(sum2, slo, shi);
        f2unpack(sq2, sqlo, sqhi);
        float sum = slo + shi;
        float sq = sqlo + sqhi;
        wredsum2(sum, sq);
        float mean = sum * (1.f / 256.f);
        float var = sq * (1.f / 256.f) - mean * mean;
        float rstd = rsqrtf(var + EPS_LN);
        u64 A2 = dup2(rstd);
        u64 Cc = dup2(-mean * rstd);

        u64 sarr[4] = {s0, s1, s2, s3};
        u64 acc2 = 0;
#pragma unroll
        for (int p = 0; p < 4; p++) {
            u64 un2 = fma2(sarr[p], A2, Cc);
            u64 z2 = fma2(un2, prm[p][lane], prm[4 + p][lane]);
            u64 az2 = z2 & AMASK;
            u64 d2 = fma2(az2, PC, ONE2);
            float dl, dh;
            f2unpack(d2, dl, dh);
            u64 t2 = f2pack(rcp_fast(dl), rcp_fast(dh));
            u64 p2 = fma2(t2, C3, C2C);
            p2 = fma2(t2, p2, C1);
            p2 = mul2(p2, t2);
            u64 zz2 = mul2(az2, az2);
            u64 m2 = mul2(zz2, NL2E);
            float ml, mh;
            f2unpack(m2, ml, mh);
            u64 e2 = f2pack(ex2_fast(ml), ex2_fast(mh));
            u64 erf2 = fma2(p2, e2, ONE2);
            erf2 = erf2 | (z2 & SMASK);
            u64 op2 = add2(erf2, ONE2);
            u64 term2 = mul2(z2, op2);
            acc2 = fma2(term2, prm[8 + p][lane], acc2);
        }
        float al, ah;
        f2unpack(acc2, al, ah);
        float acc = wredsum(al + ah);
        if (lane == 0) out[e0 + i] = acc + b2;
    }
}

// ============================================================================
// fr role: x[64] -> Linear(128) -> LN -> GELU -> Linear(64)
// GEMM1 in node-pair f32x2 (transposed xs); LN/GELU/GEMM2 scalar.
// ============================================================================
__device__ __forceinline__ void fr_role(int nb, char* smem_raw,
                                        const float* __restrict__ x,
                                        const float* __restrict__ w1,
                                        const float* __restrict__ b1,
                                        const float* __restrict__ gm,
                                        const float* __restrict__ bt,
                                        const float* __restrict__ w2,
                                        const float* __restrict__ b2,
                                        float* __restrict__ out, int N) {
    const int t = threadIdx.x;
    const int g = t >> 6;
    const int t64 = t & 63;
    float (*xs)[16] = reinterpret_cast<float (*)[16]>(smem_raw + g * 4096);   // [64][16]
    float (*hs)[128] = reinterpret_cast<float (*)[128]>(smem_raw + 8192 + g * 8192);
    const int n0 = nb * 32 + g * 16;

    {
        const float4* x4 = reinterpret_cast<const float4*>(x);
#pragma unroll
        for (int i = t64; i < 256; i += 64) {
            int node = i >> 4, kq = i & 15;
            float4 v = make_float4(0.f, 0.f, 0.f, 0.f);
            if (n0 + node < N) v = x4[(size_t)(n0 + node) * 16 + kq];
            xs[kq * 4 + 0][node] = v.x;
            xs[kq * 4 + 1][node] = v.y;
            xs[kq * 4 + 2][node] = v.z;
            xs[kq * 4 + 3][node] = v.w;
        }
    }
    __syncthreads();

    // GEMM1: node-pair f32x2, cols c0=t64, c1=t64+64
    {
        u64 a0[8], a1[8];
#pragma unroll
        for (int p = 0; p < 8; p++) { a0[p] = 0; a1[p] = 0; }
        const int c0 = t64, c1 = t64 + 64;
#pragma unroll 4
        for (int k = 0; k < 64; k++) {
            u64 w0 = dup2(w1[k * 128 + c0]);
            u64 wB = dup2(w1[k * 128 + c1]);
#pragma unroll
            for (int p = 0; p < 8; p++) {
                u64 xv = *reinterpret_cast<const u64*>(&xs[k][2 * p]);
                a0[p] = fma2(xv, w0, a0[p]);
                a1[p] = fma2(xv, wB, a1[p]);
            }
        }
        float bb0 = b1[c0], bb1 = b1[c1];
#pragma unroll
        for (int p = 0; p < 8; p++) {
            float lo, hi;
            f2unpack(a0[p], lo, hi);
            hs[2 * p][c0] = lo + bb0;
            hs[2 * p + 1][c0] = hi + bb0;
            f2unpack(a1[p], lo, hi);
            hs[2 * p][c1] = lo + bb1;
            hs[2 * p + 1][c1] = hi + bb1;
        }
    }
    __syncthreads();

    {
        const int w2i = t64 >> 5, lane = t & 31;
        float rg[4], rb[4];
#pragma unroll
        for (int q = 0; q < 4; q++) { rg[q] = gm[lane + 32 * q]; rb[q] = bt[lane + 32 * q]; }
        for (int mm = 0; mm < 8; mm++) {
            int m = w2i * 8 + mm;
            float v[4];
            float sum = 0.f, sq = 0.f;
#pragma unroll
            for (int q = 0; q < 4; q++) {
                v[q] = hs[m][lane + 32 * q];
                sum += v[q];
                sq = fmaf(v[q], v[q], sq);
            }
            wredsum2(sum, sq);
            float mean = sum * (1.f / 128.f);
            float var = sq * (1.f / 128.f) - mean * mean;
            float rstd = rsqrtf(var + EPS_LN);
#pragma unroll
            for (int q = 0; q < 4; q++) {
                float u = fmaf((v[q] - mean) * rstd, rg[q], rb[q]);
                hs[m][lane + 32 * q] = gelu_fast(u);
            }
        }
    }
    __syncthreads();

    {
        const int mg = t64 >> 5;
        const int o0 = (t & 31) * 2;
        float acc[8][2];
#pragma unroll
        for (int mm = 0; mm < 8; mm++) { acc[mm][0] = 0.f; acc[mm][1] = 0.f; }
#pragma unroll 2
        for (int j4 = 0; j4 < 32; j4++) {
            float2 wv[4];
#pragma unroll
            for (int j = 0; j < 4; j++)
                wv[j] = *reinterpret_cast<const float2*>(&w2[(j4 * 4 + j) * 64 + o0]);
#pragma unroll
            for (int mm = 0; mm < 8; mm++) {
                int m = mg * 8 + mm;
                float4 gv = *reinterpret_cast<const float4*>(&hs[m][j4 * 4]);
                acc[mm][0] = fmaf(gv.x, wv[0].x, acc[mm][0]);
                acc[mm][0] = fmaf(gv.y, wv[1].x, acc[mm][0]);
                acc[mm][0] = fmaf(gv.z, wv[2].x, acc[mm][0]);
                acc[mm][0] = fmaf(gv.w, wv[3].x, acc[mm][0]);
                acc[mm][1] = fmaf(gv.x, wv[0].y, acc[mm][1]);
                acc[mm][1] = fmaf(gv.y, wv[1].y, acc[mm][1]);
                acc[mm][1] = fmaf(gv.z, wv[2].y, acc[mm][1]);
                acc[mm][1] = fmaf(gv.w, wv[3].y, acc[mm][1]);
            }
        }
        float bo0 = b2[o0], bo1 = b2[o0 + 1];
#pragma unroll
        for (int mm = 0; mm < 8; mm++) {
            int n = n0 + mg * 8 + mm;
            if (n < N) {
                out[(size_t)n * 64 + o0] = acc[mm][0] + bo0;
                out[(size_t)n * 64 + o0 + 1] = acc[mm][1] + bo1;
            }
        }
    }
}

// ============================================================================
// ph role: x[64] -> Linear(256) -> LN -> GELU -> Linear(128)
// GEMM1 in node-pair f32x2 (transposed xs); LN/GELU/GEMM2 scalar.
// ============================================================================
__device__ __forceinline__ void ph_role(int nb, char* smem_raw,
                                        const float* __restrict__ x,
                                        const float* __restrict__ w1,
                                        const float* __restrict__ b1,
                                        const float* __restrict__ gm,
                                        const float* __restrict__ bt,
                                        const float* __restrict__ w2,
                                        const float* __restrict__ b2,
                                        float* __restrict__ out, int N) {
    const int t = threadIdx.x;
    const int g = t >> 6;
    const int t64 = t & 63;
    float (*xs)[8] = reinterpret_cast<float (*)[8]>(smem_raw + g * 2048);     // [64][8]
    float (*hs)[256] = reinterpret_cast<float (*)[256]>(smem_raw + 4096 + g * 8192);
    const int n0 = nb * 16 + g * 8;

    {
        const float4* x4 = reinterpret_cast<const float4*>(x);
#pragma unroll
        for (int i = t64; i < 128; i += 64) {
            int node = i >> 4, kq = i & 15;
            float4 v = make_float4(0.f, 0.f, 0.f, 0.f);
            if (n0 + node < N) v = x4[(size_t)(n0 + node) * 16 + kq];
            xs[kq * 4 + 0][node] = v.x;
            xs[kq * 4 + 1][node] = v.y;
            xs[kq * 4 + 2][node] = v.z;
            xs[kq * 4 + 3][node] = v.w;
        }
    }
    __syncthreads();

    // GEMM1: node-pair f32x2, 4 cols/thread
    {
        u64 a[4][4];
#pragma unroll
        for (int cc = 0; cc < 4; cc++)
#pragma unroll
            for (int p = 0; p < 4; p++) a[cc][p] = 0;

#pragma unroll 4
        for (int k = 0; k < 64; k++) {
            u64 wr[4];
#pragma unroll
            for (int cc = 0; cc < 4; cc++)
                wr[cc] = dup2(w1[k * 256 + t64 + 64 * cc]);
#pragma unroll
            for (int p = 0; p < 4; p++) {
                u64 xv = *reinterpret_cast<const u64*>(&xs[k][2 * p]);
#pragma unroll
                for (int cc = 0; cc < 4; cc++) a[cc][p] = fma2(xv, wr[cc], a[cc][p]);
            }
        }
#pragma unroll
        for (int cc = 0; cc < 4; cc++) {
            float bb = b1[t64 + 64 * cc];
#pragma unroll
            for (int p = 0; p < 4; p++) {
                float lo, hi;
                f2unpack(a[cc][p], lo, hi);
                hs[2 * p][t64 + 64 * cc] = lo + bb;
                hs[2 * p + 1][t64 + 64 * cc] = hi + bb;
            }
        }
    }
    __syncthreads();

    {
        const int w2i = t64 >> 5, lane = t & 31;
        float rg[8], rb[8];
#pragma unroll
        for (int q = 0; q < 8; q++) { rg[q] = gm[lane + 32 * q]; rb[q] = bt[lane + 32 * q]; }
        for (int mm = 0; mm < 4; mm++) {
            int m = w2i * 4 + mm;
            float v[8];
            float sum = 0.f, sq = 0.f;
#pragma unroll
            for (int q = 0; q < 8; q++) {
                v[q] = hs[m][lane + 32 * q];
                sum += v[q];
                sq = fmaf(v[q], v[q], sq);
            }
            wredsum2(sum, sq);
            float mean = sum * (1.f / 256.f);
            float var = sq * (1.f / 256.f) - mean * mean;
            float rstd = rsqrtf(var + EPS_LN);
#pragma unroll
            for (int q = 0; q < 8; q++) {
                float u = fmaf((v[q] - mean) * rstd, rg[q], rb[q]);
                hs[m][lane + 32 * q] = gelu_fast(u);
            }
        }
    }
    __syncthreads();

    {
        const int mg = t64 >> 5;
        const int o0 = (t & 31) * 4;
        float acc[4][4];
#pragma unroll
        for (int mm = 0; mm < 4; mm++)
#pragma unroll
            for (int oo = 0; oo < 4; oo++) acc[mm][oo] = 0.f;

#pragma unroll 2
        for (int j4 = 0; j4 < 64; j4++) {
            float4 wv[4];
#pragma unroll
            for (int j = 0; j < 4; j++)
                wv[j] = *reinterpret_cast<const float4*>(&w2[(j4 * 4 + j) * 128 + o0]);
#pragma unroll
            for (int mm = 0; mm < 4; mm++) {
                int m = mg * 4 + mm;
                float4 gv = *reinterpret_cast<const float4*>(&hs[m][j4 * 4]);
                float gvals[4] = {gv.x, gv.y, gv.z, gv.w};
#pragma unroll
                for (int j = 0; j < 4; j++) {
                    acc[mm][0] = fmaf(gvals[j], wv[j].x, acc[mm][0]);
                    acc[mm][1] = fmaf(gvals[j], wv[j].y, acc[mm][1]);
                    acc[mm][2] = fmaf(gvals[j], wv[j].z, acc[mm][2]);
                    acc[mm][3] = fmaf(gvals[j], wv[j].w, acc[mm][3]);
                }
            }
        }
        float4 bo = *reinterpret_cast<const float4*>(&b2[o0]);
#pragma unroll
        for (int mm = 0; mm < 4; mm++) {
            int n = n0 + mg * 4 + mm;
            if (n < N) {
                float4 rr;
                rr.x = acc[mm][0] + bo.x;
                rr.y = acc[mm][1] + bo.y;
                rr.z = acc[mm][2] + bo.z;
                rr.w = acc[mm][3] + bo.w;
                *reinterpret_cast<float4*>(&out[(size_t)n * 128 + o0]) = rr;
            }
        }
    }
}

// ============================================================================
// Mega kernel: role-interleaved edge + fr + ph (8:3 block pattern), occ 8
// ============================================================================
__global__ __launch_bounds__(128, 8) void k_mega(
    const float* __restrict__ x, const int* __restrict__ ei, int N, int E,
    const float* __restrict__ fr_w1, const float* __restrict__ fr_b1,
    const float* __restrict__ fr_g, const float* __restrict__ fr_be,
    const float* __restrict__ fr_w2, const float* __restrict__ fr_b2,
    const float* __restrict__ ph_w1, const float* __restrict__ ph_b1,
    const float* __restrict__ ph_g, const float* __restrict__ ph_be,
    const float* __restrict__ ph_w2, const float* __restrict__ ph_b2,
    const float* __restrict__ sp_g, const float* __restrict__ sp_be,
    const float* __restrict__ sp_w2, const float* __restrict__ sp_b2,
    float* __restrict__ out_sp, float* __restrict__ out_fr, float* __restrict__ out_ph,
    int nfr, int nph) {
    __shared__ __align__(16) char smem_raw[24576];
    const int b = blockIdx.x;
    const int gid = b / 11;
    const int slot = b - gid * 11;

    if (slot < 8) {
        edge_role(gid * 8 + slot, smem_raw, ei, E, sp_g, sp_be, sp_w2, sp_b2, out_sp);
    } else {
        int nb = gid * 3 + (slot - 8);
        if (nb < nfr) {
            fr_role(nb, smem_raw, x, fr_w1, fr_b1, fr_g, fr_be, fr_w2, fr_b2, out_fr, N);
        } else if (nb < nfr + nph) {
            ph_role(nb - nfr, smem_raw, x, ph_w1, ph_b1, ph_g, ph_be, ph_w2, ph_b2, out_ph, N);
        }
    }
}

// ============================================================================
// launch
// ============================================================================
extern "C" void kernel_launch(void* const* d_in, const int* in_sizes, int n_in,
                              void* d_out, int out_size) {
    const float* x = (const float*)d_in[0];
    const int* ei = (const int*)d_in[1];
    const float* sp_w1 = (const float*)d_in[2];
    const float* sp_b1 = (const float*)d_in[3];
    const float* sp_g = (const float*)d_in[4];
    const float* sp_be = (const float*)d_in[5];
    const float* sp_w2 = (const float*)d_in[6];
    const float* sp_b2 = (const float*)d_in[7];
    const float* fr_w1 = (const float*)d_in[8];
    const float* fr_b1 = (const float*)d_in[9];
    const float* fr_g = (const float*)d_in[10];
    const float* fr_be = (const float*)d_in[11];
    const float* fr_w2 = (const float*)d_in[12];
    const float* fr_b2 = (const float*)d_in[13];
    const float* ph_w1 = (const float*)d_in[14];
    const float* ph_b1 = (const float*)d_in[15];
    const float* ph_g = (const float*)d_in[16];
    const float* ph_be = (const float*)d_in[17];
    const float* ph_w2 = (const float*)d_in[18];
    const float* ph_b2 = (const float*)d_in[19];

    const int N = in_sizes[0] / 64;
    const int E = in_sizes[1] / 2;

    float* out_sp = (float*)d_out;             // [E]
    float* out_fr = out_sp + (size_t)E;        // [N,64]
    float* out_ph = out_fr + (size_t)N * 64;   // [N,128]

    // Phase 1: P/Q precompute (edge branch depends on it)
    k_pq<<<(N + 31) / 32, 256>>>(x, sp_w1, sp_b1, N);

    // Phase 2: role-interleaved mega kernel
    const int nfr = (N + 31) / 32;
    const int nph = (N + 15) / 16;
    const int node_blocks = nfr + nph;
    const long ewarps = ((long)E + EPW - 1) / EPW;
    const int eblk = (int)((ewarps + 3) / 4);
    int Ga = (node_blocks + 2) / 3;
    int Gb = (eblk + 7) / 8;
    int G = Ga > Gb ? Ga : Gb;

    k_mega<<<G * 11, 128>>>(x, ei, N, E,
                            fr_w1, fr_b1, fr_g, fr_be, fr_w2, fr_b2,
                            ph_w1, ph_b1, ph_g, ph_be, ph_w2, ph_b2,
                            sp_g, sp_be, sp_w2, sp_b2,
                            out_sp, out_fr, out_ph, nfr, nph);
}

// round 14
// speedup vs baseline: 1.0323x; 1.0323x over previous
#include <cuda_runtime.h>
#include <stdint.h>
#include <math.h>

#define NMAX 50000
#define EPS_LN 1e-5f
#define EPW 16

typedef unsigned long long u64;

// Scratch: P = x @ sp_w1[0:64,:] + sp_b1, Q = x @ sp_w1[64:128,:]   (each [N,256])
__device__ float g_P[(size_t)NMAX * 256];
__device__ float g_Q[(size_t)NMAX * 256];

// ---------------- f32x2 packed helpers ----------------
__device__ __forceinline__ u64 f2pack(float lo, float hi) {
    u64 r; asm("mov.b64 %0, {%1, %2};" : "=l"(r) : "f"(lo), "f"(hi)); return r;
}
__device__ __forceinline__ void f2unpack(u64 v, float& lo, float& hi) {
    asm("mov.b64 {%0, %1}, %2;" : "=f"(lo), "=f"(hi) : "l"(v));
}
__device__ __forceinline__ u64 dup2(float v) { return f2pack(v, v); }
__device__ __forceinline__ u64 fma2(u64 a, u64 b, u64 c) {
    u64 d; asm("fma.rn.f32x2 %0, %1, %2, %3;" : "=l"(d) : "l"(a), "l"(b), "l"(c)); return d;
}
__device__ __forceinline__ u64 add2(u64 a, u64 b) {
    u64 d; asm("add.rn.f32x2 %0, %1, %2;" : "=l"(d) : "l"(a), "l"(b)); return d;
}
__device__ __forceinline__ u64 mul2(u64 a, u64 b) {
    u64 d; asm("mul.rn.f32x2 %0, %1, %2;" : "=l"(d) : "l"(a), "l"(b)); return d;
}
__device__ __forceinline__ float rcp_fast(float x) {
    float r; asm("rcp.approx.f32 %0, %1;" : "=f"(r) : "f"(x)); return r;
}
__device__ __forceinline__ float ex2_fast(float x) {
    float r; asm("ex2.approx.f32 %0, %1;" : "=f"(r) : "f"(x)); return r;
}

__device__ __forceinline__ float wredsum(float v) {
#pragma unroll
    for (int o = 16; o > 0; o >>= 1) v += __shfl_xor_sync(0xffffffffu, v, o);
    return v;
}
__device__ __forceinline__ void wredsum2(float& a, float& b) {
#pragma unroll
    for (int o = 16; o > 0; o >>= 1) {
        float ta = __shfl_xor_sync(0xffffffffu, a, o);
        float tb = __shfl_xor_sync(0xffffffffu, b, o);
        a += ta;
        b += tb;
    }
}
__device__ __forceinline__ void wredsum4(float& a, float& b, float& c, float& d) {
#pragma unroll
    for (int o = 16; o > 0; o >>= 1) {
        float ta = __shfl_xor_sync(0xffffffffu, a, o);
        float tb = __shfl_xor_sync(0xffffffffu, b, o);
        float tc = __shfl_xor_sync(0xffffffffu, c, o);
        float td = __shfl_xor_sync(0xffffffffu, d, o);
        a += ta; b += tb; c += tc; d += td;
    }
}

// fast GELU, sign-free: u*(1+erf(z)) = u + |u| - |u|*poly*e   (z = u/sqrt2)
__device__ __forceinline__ float gelu_fast(float u) {
    float z = 0.70710678118654752f * u;
    float az = fabsf(z);
    float au = fabsf(u);
    float t = rcp_fast(fmaf(0.47047f, az, 1.0f));
    float poly = t * fmaf(t, fmaf(t, 0.7478556f, -0.0958798f), 0.3480242f);
    float e = ex2_fast(-az * az * 1.4426950408889634f);
    return 0.5f * fmaf(-au * poly, e, u + au);
}

// ============================================================================
// K1: P,Q = x @ W_top (+b1), x @ W_bot.  32-node tile, 256 threads, scalar.
// ============================================================================
__global__ __launch_bounds__(256) void k_pq(const float* __restrict__ x,
                                            const float* __restrict__ w,   // [128,256]
                                            const float* __restrict__ b1,  // [256]
                                            int N) {
    __shared__ float xs[32][64];
    const int t = threadIdx.x;
    const int n0 = blockIdx.x * 32;

    {
        float4* xs4 = reinterpret_cast<float4*>(&xs[0][0]);
        const float4* x4 = reinterpret_cast<const float4*>(x);
#pragma unroll
        for (int i = t; i < 512; i += 256) {
            int node = n0 + (i >> 4);
            float4 v = make_float4(0.f, 0.f, 0.f, 0.f);
            if (node < N) v = x4[(size_t)node * 16 + (i & 15)];
            xs4[i] = v;
        }
    }
    __syncthreads();

    float aP[32], aQ[32];
#pragma unroll
    for (int m = 0; m < 32; m++) { aP[m] = 0.f; aQ[m] = 0.f; }

    const int c = t;
#pragma unroll 2
    for (int k4 = 0; k4 < 16; k4++) {
        float wp[4], wq[4];
#pragma unroll
        for (int j = 0; j < 4; j++) {
            int k = k4 * 4 + j;
            wp[j] = w[k * 256 + c];
            wq[j] = w[(64 + k) * 256 + c];
        }
#pragma unroll
        for (int m = 0; m < 32; m++) {
            float4 xv = *reinterpret_cast<const float4*>(&xs[m][k4 * 4]);
            float xa[4] = {xv.x, xv.y, xv.z, xv.w};
#pragma unroll
            for (int j = 0; j < 4; j++) {
                aP[m] = fmaf(xa[j], wp[j], aP[m]);
                aQ[m] = fmaf(xa[j], wq[j], aQ[m]);
            }
        }
    }

    const float bb = b1[c];
#pragma unroll
    for (int m = 0; m < 32; m++) {
        int n = n0 + m;
        if (n >= N) break;
        g_P[(size_t)n * 256 + c] = aP[m] + bb;
        g_Q[(size_t)n * 256 + c] = aQ[m];
    }
}

// ============================================================================
// Edge role: out = GELU(LN(P[row]+Q[col])) . w2 + b2  — dual-edge, f32x2,
// sign-free erf tail: z(1+erf) = (z+|z|) - (|z|*poly)*e
// ============================================================================
__device__ __forceinline__ void edge_role(int eb, const int* __restrict__ ei, int E,
                                          const float* __restrict__ gm,
                                          const float* __restrict__ bt,
                                          const float* __restrict__ w2,
                                          const float* __restrict__ b2p,
                                          float* __restrict__ out) {
    const int t = threadIdx.x;
    const int lane = t & 31;
    const int wid = t >> 5;

    long e0 = ((long)eb * 4 + wid) * EPW;
    if (e0 >= E) return;
    const int nE = (int)(E - e0 < EPW ? E - e0 : EPW);

    const float4* gmv = reinterpret_cast<const float4*>(gm);
    const float4* btv = reinterpret_cast<const float4*>(bt);
    const float4* w2v = reinterpret_cast<const float4*>(w2);
    float4 rga = gmv[lane], rgb = gmv[32 + lane];
    float4 rba = btv[lane], rbb = btv[32 + lane];
    float4 rwa = w2v[lane], rwb = w2v[32 + lane];

    const float RS2 = 0.70710678118654752f;
    u64 g2[4] = {f2pack(rga.x * RS2, rga.y * RS2), f2pack(rga.z * RS2, rga.w * RS2),
                 f2pack(rgb.x * RS2, rgb.y * RS2), f2pack(rgb.z * RS2, rgb.w * RS2)};
    u64 be2[4] = {f2pack(rba.x * RS2, rba.y * RS2), f2pack(rba.z * RS2, rba.w * RS2),
                  f2pack(rbb.x * RS2, rbb.y * RS2), f2pack(rbb.z * RS2, rbb.w * RS2)};
    u64 hw2[4] = {f2pack(rwa.x * RS2, rwa.y * RS2), f2pack(rwa.z * RS2, rwa.w * RS2),
                  f2pack(rwb.x * RS2, rwb.y * RS2), f2pack(rwb.z * RS2, rwb.w * RS2)};

    const u64 ONE2 = dup2(1.0f);
    const u64 PC = dup2(0.47047f);
    const u64 C3 = dup2(-0.7478556f);
    const u64 C2C = dup2(0.0958798f);
    const u64 C1 = dup2(-0.3480242f);
    const u64 NL2E = dup2(-1.4426950408889634f);
    const u64 AMASK = 0x7FFFFFFF7FFFFFFFull;

    const float b2 = __ldg(b2p);

    const ulonglong2* P2v = reinterpret_cast<const ulonglong2*>(g_P);
    const ulonglong2* Q2v = reinterpret_cast<const ulonglong2*>(g_Q);

    const int li = lane & 15;
    int idx = 0;
    if (li < nE) idx = ei[(lane < 16 ? e0 + li : (long)E + e0 + li)];

    for (int i = 0; i < nE; i += 2) {
        const int i2 = (i + 1 < nE) ? i + 1 : i;
        int rA = __shfl_sync(0xffffffffu, idx, i);
        int cA = __shfl_sync(0xffffffffu, idx, 16 + i);
        int rB = __shfl_sync(0xffffffffu, idx, i2);
        int cB = __shfl_sync(0xffffffffu, idx, 16 + i2);

        ulonglong2 paA = P2v[(size_t)rA * 64 + lane];
        ulonglong2 pbA = P2v[(size_t)rA * 64 + 32 + lane];
        ulonglong2 qaA = Q2v[(size_t)cA * 64 + lane];
        ulonglong2 qbA = Q2v[(size_t)cA * 64 + 32 + lane];
        ulonglong2 paB = P2v[(size_t)rB * 64 + lane];
        ulonglong2 pbB = P2v[(size_t)rB * 64 + 32 + lane];
        ulonglong2 qaB = Q2v[(size_t)cB * 64 + lane];
        ulonglong2 qbB = Q2v[(size_t)cB * 64 + 32 + lane];

        u64 sA[4], sB[4];
        sA[0] = add2(paA.x, qaA.x);
        sA[1] = add2(paA.y, qaA.y);
        sA[2] = add2(pbA.x, qbA.x);
        sA[3] = add2(pbA.y, qbA.y);
        sB[0] = add2(paB.x, qaB.x);
        sB[1] = add2(paB.y, qaB.y);
        sB[2] = add2(pbB.x, qbB.x);
        sB[3] = add2(pbB.y, qbB.y);

        u64 sumA2 = add2(add2(sA[0], sA[1]), add2(sA[2], sA[3]));
        u64 sqA2 = fma2(sA[0], sA[0], fma2(sA[1], sA[1], fma2(sA[2], sA[2], mul2(sA[3], sA[3]))));
        u64 sumB2 = add2(add2(sB[0], sB[1]), add2(sB[2], sB[3]));
        u64 sqB2 = fma2(sB[0], sB[0], fma2(sB[1], sB[1], fma2(sB[2], sB[2], mul2(sB[3], sB[3]))));

        float xl, xh;
        f2unpack(sumA2, xl, xh);
        float sumA = xl + xh;
        f2unpack(sqA2, xl, xh);
        float sqA = xl + xh;
        f2unpack(sumB2, xl, xh);
        float sumB = xl + xh;
        f2unpack(sqB2, xl, xh);
        float sqB = xl + xh;

        wredsum4(sumA, sqA, sumB, sqB);

        float meanA = sumA * (1.f / 256.f);
        float varA = sqA * (1.f / 256.f) - meanA * meanA;
        float rstdA = rsqrtf(varA + EPS_LN);
        float meanB = sumB * (1.f / 256.f);
        float varB = sqB * (1.f / 256.f) - meanB * meanB;
        float rstdB = rsqrtf(varB + EPS_LN);

        u64 A2a = dup2(rstdA), Cca = dup2(-meanA * rstdA);
        u64 A2b = dup2(rstdB), Ccb = dup2(-meanB * rstdB);

        u64 accA = 0, accB = 0;
#pragma unroll
        for (int p = 0; p < 4; p++) {
            u64 uA = fma2(sA[p], A2a, Cca);
            u64 uB = fma2(sB[p], A2b, Ccb);
            u64 zA = fma2(uA, g2[p], be2[p]);
            u64 zB = fma2(uB, g2[p], be2[p]);
            u64 azA = zA & AMASK;
            u64 azB = zB & AMASK;
            u64 dA = fma2(azA, PC, ONE2);
            u64 dB = fma2(azB, PC, ONE2);
            float dAl, dAh, dBl, dBh;
            f2unpack(dA, dAl, dAh);
            f2unpack(dB, dBl, dBh);
            u64 tA = f2pack(rcp_fast(dAl), rcp_fast(dAh));
            u64 tB = f2pack(rcp_fast(dBl), rcp_fast(dBh));
            u64 pA = fma2(tA, C3, C2C);
            u64 pB = fma2(tB, C3, C2C);
            pA = fma2(tA, pA, C1);
            pB = fma2(tB, pB, C1);
            pA = mul2(pA, tA);               // -poly (negated coeffs)
            pB = mul2(pB, tB);
            u64 zzA = mul2(azA, azA);
            u64 zzB = mul2(azB, azB);
            u64 mA = mul2(zzA, NL2E);
            u64 mB = mul2(zzB, NL2E);
            float mAl, mAh, mBl, mBh;
            f2unpack(mA, mAl, mAh);
            f2unpack(mB, mBl, mBh);
            u64 eA = f2pack(ex2_fast(mAl), ex2_fast(mAh));
            u64 eB = f2pack(ex2_fast(mBl), ex2_fast(mBh));
            // z*(1+erf(z)) = (z+|z|) + (|z|*(-poly))*e   [sign-free]
            u64 zpazA = add2(zA, azA);
            u64 zpazB = add2(zB, azB);
            u64 wA = mul2(azA, pA);
            u64 wB = mul2(azB, pB);
            u64 termA = fma2(wA, eA, zpazA);
            u64 termB = fma2(wB, eB, zpazB);
            accA = fma2(termA, hw2[p], accA);
            accB = fma2(termB, hw2[p], accB);
        }
        float aAl, aAh, aBl, aBh;
        f2unpack(accA, aAl, aAh);
        f2unpack(accB, aBl, aBh);
        float fA = aAl + aAh, fB = aBl + aBh;
        wredsum2(fA, fB);
        if (lane == 0) {
            out[e0 + i] = fA + b2;
            if (i + 1 < nE) out[e0 + i + 1] = fB + b2;
        }
    }
}

// ============================================================================
// fr role: x[64] -> Linear(128) -> LN -> GELU -> Linear(64)
// GEMM1 in node-pair f32x2 (transposed xs); LN/GELU/GEMM2 scalar.
// ============================================================================
__device__ __forceinline__ void fr_role(int nb, char* smem_raw,
                                        const float* __restrict__ x,
                                        const float* __restrict__ w1,
                                        const float* __restrict__ b1,
                                        const float* __restrict__ gm,
                                        const float* __restrict__ bt,
                                        const float* __restrict__ w2,
                                        const float* __restrict__ b2,
                                        float* __restrict__ out, int N) {
    const int t = threadIdx.x;
    const int g = t >> 6;
    const int t64 = t & 63;
    float (*xs)[16] = reinterpret_cast<float (*)[16]>(smem_raw + g * 4096);   // [64][16]
    float (*hs)[128] = reinterpret_cast<float (*)[128]>(smem_raw + 8192 + g * 8192);
    const int n0 = nb * 32 + g * 16;

    {
        const float4* x4 = reinterpret_cast<const float4*>(x);
#pragma unroll
        for (int i = t64; i < 256; i += 64) {
            int node = i >> 4, kq = i & 15;
            float4 v = make_float4(0.f, 0.f, 0.f, 0.f);
            if (n0 + node < N) v = x4[(size_t)(n0 + node) * 16 + kq];
            xs[kq * 4 + 0][node] = v.x;
            xs[kq * 4 + 1][node] = v.y;
            xs[kq * 4 + 2][node] = v.z;
            xs[kq * 4 + 3][node] = v.w;
        }
    }
    __syncthreads();

    // GEMM1: node-pair f32x2, cols c0=t64, c1=t64+64
    {
        u64 a0[8], a1[8];
#pragma unroll
        for (int p = 0; p < 8; p++) { a0[p] = 0; a1[p] = 0; }
        const int c0 = t64, c1 = t64 + 64;
#pragma unroll 4
        for (int k = 0; k < 64; k++) {
            u64 w0 = dup2(w1[k * 128 + c0]);
            u64 wB = dup2(w1[k * 128 + c1]);
#pragma unroll
            for (int p = 0; p < 8; p++) {
                u64 xv = *reinterpret_cast<const u64*>(&xs[k][2 * p]);
                a0[p] = fma2(xv, w0, a0[p]);
                a1[p] = fma2(xv, wB, a1[p]);
            }
        }
        float bb0 = b1[c0], bb1 = b1[c1];
#pragma unroll
        for (int p = 0; p < 8; p++) {
            float lo, hi;
            f2unpack(a0[p], lo, hi);
            hs[2 * p][c0] = lo + bb0;
            hs[2 * p + 1][c0] = hi + bb0;
            f2unpack(a1[p], lo, hi);
            hs[2 * p][c1] = lo + bb1;
            hs[2 * p + 1][c1] = hi + bb1;
        }
    }
    __syncthreads();

    {
        const int w2i = t64 >> 5, lane = t & 31;
        float rg[4], rb[4];
#pragma unroll
        for (int q = 0; q < 4; q++) { rg[q] = gm[lane + 32 * q]; rb[q] = bt[lane + 32 * q]; }
        for (int mm = 0; mm < 8; mm++) {
            int m = w2i * 8 + mm;
            float v[4];
            float sum = 0.f, sq = 0.f;
#pragma unroll
            for (int q = 0; q < 4; q++) {
                v[q] = hs[m][lane + 32 * q];
                sum += v[q];
                sq = fmaf(v[q], v[q], sq);
            }
            wredsum2(sum, sq);
            float mean = sum * (1.f / 128.f);
            float var = sq * (1.f / 128.f) - mean * mean;
            float rstd = rsqrtf(var + EPS_LN);
#pragma unroll
            for (int q = 0; q < 4; q++) {
                float u = fmaf((v[q] - mean) * rstd, rg[q], rb[q]);
                hs[m][lane + 32 * q] = gelu_fast(u);
            }
        }
    }
    __syncthreads();

    {
        const int mg = t64 >> 5;
        const int o0 = (t & 31) * 2;
        float acc[8][2];
#pragma unroll
        for (int mm = 0; mm < 8; mm++) { acc[mm][0] = 0.f; acc[mm][1] = 0.f; }
#pragma unroll 2
        for (int j4 = 0; j4 < 32; j4++) {
            float2 wv[4];
#pragma unroll
            for (int j = 0; j < 4; j++)
                wv[j] = *reinterpret_cast<const float2*>(&w2[(j4 * 4 + j) * 64 + o0]);
#pragma unroll
            for (int mm = 0; mm < 8; mm++) {
                int m = mg * 8 + mm;
                float4 gv = *reinterpret_cast<const float4*>(&hs[m][j4 * 4]);
                acc[mm][0] = fmaf(gv.x, wv[0].x, acc[mm][0]);
                acc[mm][0] = fmaf(gv.y, wv[1].x, acc[mm][0]);
                acc[mm][0] = fmaf(gv.z, wv[2].x, acc[mm][0]);
                acc[mm][0] = fmaf(gv.w, wv[3].x, acc[mm][0]);
                acc[mm][1] = fmaf(gv.x, wv[0].y, acc[mm][1]);
                acc[mm][1] = fmaf(gv.y, wv[1].y, acc[mm][1]);
                acc[mm][1] = fmaf(gv.z, wv[2].y, acc[mm][1]);
                acc[mm][1] = fmaf(gv.w, wv[3].y, acc[mm][1]);
            }
        }
        float bo0 = b2[o0], bo1 = b2[o0 + 1];
#pragma unroll
        for (int mm = 0; mm < 8; mm++) {
            int n = n0 + mg * 8 + mm;
            if (n < N) {
                out[(size_t)n * 64 + o0] = acc[mm][0] + bo0;
                out[(size_t)n * 64 + o0 + 1] = acc[mm][1] + bo1;
            }
        }
    }
}

// ============================================================================
// ph role: x[64] -> Linear(256) -> LN -> GELU -> Linear(128)
// GEMM1 in node-pair f32x2 (transposed xs); LN/GELU/GEMM2 scalar.
// ============================================================================
__device__ __forceinline__ void ph_role(int nb, char* smem_raw,
                                        const float* __restrict__ x,
                                        const float* __restrict__ w1,
                                        const float* __restrict__ b1,
                                        const float* __restrict__ gm,
                                        const float* __restrict__ bt,
                                        const float* __restrict__ w2,
                                        const float* __restrict__ b2,
                                        float* __restrict__ out, int N) {
    const int t = threadIdx.x;
    const int g = t >> 6;
    const int t64 = t & 63;
    float (*xs)[8] = reinterpret_cast<float (*)[8]>(smem_raw + g * 2048);     // [64][8]
    float (*hs)[256] = reinterpret_cast<float (*)[256]>(smem_raw + 4096 + g * 8192);
    const int n0 = nb * 16 + g * 8;

    {
        const float4* x4 = reinterpret_cast<const float4*>(x);
#pragma unroll
        for (int i = t64; i < 128; i += 64) {
            int node = i >> 4, kq = i & 15;
            float4 v = make_float4(0.f, 0.f, 0.f, 0.f);
            if (n0 + node < N) v = x4[(size_t)(n0 + node) * 16 + kq];
            xs[kq * 4 + 0][node] = v.x;
            xs[kq * 4 + 1][node] = v.y;
            xs[kq * 4 + 2][node] = v.z;
            xs[kq * 4 + 3][node] = v.w;
        }
    }
    __syncthreads();

    // GEMM1: node-pair f32x2, 4 cols/thread
    {
        u64 a[4][4];
#pragma unroll
        for (int cc = 0; cc < 4; cc++)
#pragma unroll
            for (int p = 0; p < 4; p++) a[cc][p] = 0;

#pragma unroll 4
        for (int k = 0; k < 64; k++) {
            u64 wr[4];
#pragma unroll
            for (int cc = 0; cc < 4; cc++)
                wr[cc] = dup2(w1[k * 256 + t64 + 64 * cc]);
#pragma unroll
            for (int p = 0; p < 4; p++) {
                u64 xv = *reinterpret_cast<const u64*>(&xs[k][2 * p]);
#pragma unroll
                for (int cc = 0; cc < 4; cc++) a[cc][p] = fma2(xv, wr[cc], a[cc][p]);
            }
        }
#pragma unroll
        for (int cc = 0; cc < 4; cc++) {
            float bb = b1[t64 + 64 * cc];
#pragma unroll
            for (int p = 0; p < 4; p++) {
                float lo, hi;
                f2unpack(a[cc][p], lo, hi);
                hs[2 * p][t64 + 64 * cc] = lo + bb;
                hs[2 * p + 1][t64 + 64 * cc] = hi + bb;
            }
        }
    }
    __syncthreads();

    {
        const int w2i = t64 >> 5, lane = t & 31;
        float rg[8], rb[8];
#pragma unroll
        for (int q = 0; q < 8; q++) { rg[q] = gm[lane + 32 * q]; rb[q] = bt[lane + 32 * q]; }
        for (int mm = 0; mm < 4; mm++) {
            int m = w2i * 4 + mm;
            float v[8];
            float sum = 0.f, sq = 0.f;
#pragma unroll
            for (int q = 0; q < 8; q++) {
                v[q] = hs[m][lane + 32 * q];
                sum += v[q];
                sq = fmaf(v[q], v[q], sq);
            }
            wredsum2(sum, sq);
            float mean = sum * (1.f / 256.f);
            float var = sq * (1.f / 256.f) - mean * mean;
            float rstd = rsqrtf(var + EPS_LN);
#pragma unroll
            for (int q = 0; q < 8; q++) {
                float u = fmaf((v[q] - mean) * rstd, rg[q], rb[q]);
                hs[m][lane + 32 * q] = gelu_fast(u);
            }
        }
    }
    __syncthreads();

    {
        const int mg = t64 >> 5;
        const int o0 = (t & 31) * 4;
        float acc[4][4];
#pragma unroll
        for (int mm = 0; mm < 4; mm++)
#pragma unroll
            for (int oo = 0; oo < 4; oo++) acc[mm][oo] = 0.f;

#pragma unroll 2
        for (int j4 = 0; j4 < 64; j4++) {
            float4 wv[4];
#pragma unroll
            for (int j = 0; j < 4; j++)
                wv[j] = *reinterpret_cast<const float4*>(&w2[(j4 * 4 + j) * 128 + o0]);
#pragma unroll
            for (int mm = 0; mm < 4; mm++) {
                int m = mg * 4 + mm;
                float4 gv = *reinterpret_cast<const float4*>(&hs[m][j4 * 4]);
                float gvals[4] = {gv.x, gv.y, gv.z, gv.w};
#pragma unroll
                for (int j = 0; j < 4; j++) {
                    acc[mm][0] = fmaf(gvals[j], wv[j].x, acc[mm][0]);
                    acc[mm][1] = fmaf(gvals[j], wv[j].y, acc[mm][1]);
                    acc[mm][2] = fmaf(gvals[j], wv[j].z, acc[mm][2]);
                    acc[mm][3] = fmaf(gvals[j], wv[j].w, acc[mm][3]);
                }
            }
        }
        float4 bo = *reinterpret_cast<const float4*>(&b2[o0]);
#pragma unroll
        for (int mm = 0; mm < 4; mm++) {
            int n = n0 + mg * 4 + mm;
            if (n < N) {
                float4 rr;
                rr.x = acc[mm][0] + bo.x;
                rr.y = acc[mm][1] + bo.y;
                rr.z = acc[mm][2] + bo.z;
                rr.w = acc[mm][3] + bo.w;
                *reinterpret_cast<float4*>(&out[(size_t)n * 128 + o0]) = rr;
            }
        }
    }
}

// ============================================================================
// Mega kernel: role-interleaved edge + fr + ph (8:3 block pattern), occ 6
// ============================================================================
__global__ __launch_bounds__(128, 6) void k_mega(
    const float* __restrict__ x, const int* __restrict__ ei, int N, int E,
    const float* __restrict__ fr_w1, const float* __restrict__ fr_b1,
    const float* __restrict__ fr_g, const float* __restrict__ fr_be,
    const float* __restrict__ fr_w2, const float* __restrict__ fr_b2,
    const float* __restrict__ ph_w1, const float* __restrict__ ph_b1,
    const float* __restrict__ ph_g, const float* __restrict__ ph_be,
    const float* __restrict__ ph_w2, const float* __restrict__ ph_b2,
    const float* __restrict__ sp_g, const float* __restrict__ sp_be,
    const float* __restrict__ sp_w2, const float* __restrict__ sp_b2,
    float* __restrict__ out_sp, float* __restrict__ out_fr, float* __restrict__ out_ph,
    int nfr, int nph) {
    __shared__ __align__(16) char smem_raw[24576];
    const int b = blockIdx.x;
    const int gid = b / 11;
    const int slot = b - gid * 11;

    if (slot < 8) {
        edge_role(gid * 8 + slot, ei, E, sp_g, sp_be, sp_w2, sp_b2, out_sp);
    } else {
        int nb = gid * 3 + (slot - 8);
        if (nb < nfr) {
            fr_role(nb, smem_raw, x, fr_w1, fr_b1, fr_g, fr_be, fr_w2, fr_b2, out_fr, N);
        } else if (nb < nfr + nph) {
            ph_role(nb - nfr, smem_raw, x, ph_w1, ph_b1, ph_g, ph_be, ph_w2, ph_b2, out_ph, N);
        }
    }
}

// ============================================================================
// launch
// ============================================================================
extern "C" void kernel_launch(void* const* d_in, const int* in_sizes, int n_in,
                              void* d_out, int out_size) {
    const float* x = (const float*)d_in[0];
    const int* ei = (const int*)d_in[1];
    const float* sp_w1 = (const float*)d_in[2];
    const float* sp_b1 = (const float*)d_in[3];
    const float* sp_g = (const float*)d_in[4];
    const float* sp_be = (const float*)d_in[5];
    const float* sp_w2 = (const float*)d_in[6];
    const float* sp_b2 = (const float*)d_in[7];
    const float* fr_w1 = (const float*)d_in[8];
    const float* fr_b1 = (const float*)d_in[9];
    const float* fr_g = (const float*)d_in[10];
    const float* fr_be = (const float*)d_in[11];
    const float* fr_w2 = (const float*)d_in[12];
    const float* fr_b2 = (const float*)d_in[13];
    const float* ph_w1 = (const float*)d_in[14];
    const float* ph_b1 = (const float*)d_in[15];
    const float* ph_g = (const float*)d_in[16];
    const float* ph_be = (const float*)d_in[17];
    const float* ph_w2 = (const float*)d_in[18];
    const float* ph_b2 = (const float*)d_in[19];

    const int N = in_sizes[0] / 64;
    const int E = in_sizes[1] / 2;

    float* out_sp = (float*)d_out;             // [E]
    float* out_fr = out_sp + (size_t)E;        // [N,64]
    float* out_ph = out_fr + (size_t)N * 64;   // [N,128]

    // Phase 1: P/Q precompute (edge branch depends on it)
    k_pq<<<(N + 31) / 32, 256>>>(x, sp_w1, sp_b1, N);

    // Phase 2: role-interleaved mega kernel
    const int nfr = (N + 31) / 32;
    const int nph = (N + 15) / 16;
    const int node_blocks = nfr + nph;
    const long ewarps = ((long)E + EPW - 1) / EPW;
    const int eblk = (int)((ewarps + 3) / 4);
    int Ga = (node_blocks + 2) / 3;
    int Gb = (eblk + 7) / 8;
    int G = Ga > Gb ? Ga : Gb;

    k_mega<<<G * 11, 128>>>(x, ei, N, E,
                            fr_w1, fr_b1, fr_g, fr_be, fr_w2, fr_b2,
                            ph_w1, ph_b1, ph_g, ph_be, ph_w2, ph_b2,
                            sp_g, sp_be, sp_w2, sp_b2,
                            out_sp, out_fr, out_ph, nfr, nph);
}

// round 15
// speedup vs baseline: 1.0463x; 1.0135x over previous
#include <cuda_runtime.h>
#include <stdint.h>
#include <math.h>

#define NMAX 50000
#define EPS_LN 1e-5f
#define EPW 16

typedef unsigned long long u64;

// Scratch: P = x @ sp_w1[0:64,:] + sp_b1, Q = x @ sp_w1[64:128,:]   (each [N,256])
__device__ float g_P[(size_t)NMAX * 256];
__device__ float g_Q[(size_t)NMAX * 256];

// ---------------- f32x2 packed helpers ----------------
__device__ __forceinline__ u64 f2pack(float lo, float hi) {
    u64 r; asm("mov.b64 %0, {%1, %2};" : "=l"(r) : "f"(lo), "f"(hi)); return r;
}
__device__ __forceinline__ void f2unpack(u64 v, float& lo, float& hi) {
    asm("mov.b64 {%0, %1}, %2;" : "=f"(lo), "=f"(hi) : "l"(v));
}
__device__ __forceinline__ u64 dup2(float v) { return f2pack(v, v); }
__device__ __forceinline__ u64 fma2(u64 a, u64 b, u64 c) {
    u64 d; asm("fma.rn.f32x2 %0, %1, %2, %3;" : "=l"(d) : "l"(a), "l"(b), "l"(c)); return d;
}
__device__ __forceinline__ u64 add2(u64 a, u64 b) {
    u64 d; asm("add.rn.f32x2 %0, %1, %2;" : "=l"(d) : "l"(a), "l"(b)); return d;
}
__device__ __forceinline__ u64 mul2(u64 a, u64 b) {
    u64 d; asm("mul.rn.f32x2 %0, %1, %2;" : "=l"(d) : "l"(a), "l"(b)); return d;
}
__device__ __forceinline__ float rcp_fast(float x) {
    float r; asm("rcp.approx.f32 %0, %1;" : "=f"(r) : "f"(x)); return r;
}
__device__ __forceinline__ float ex2_fast(float x) {
    float r; asm("ex2.approx.f32 %0, %1;" : "=f"(r) : "f"(x)); return r;
}

__device__ __forceinline__ float wredsum(float v) {
#pragma unroll
    for (int o = 16; o > 0; o >>= 1) v += __shfl_xor_sync(0xffffffffu, v, o);
    return v;
}
__device__ __forceinline__ void wredsum2(float& a, float& b) {
#pragma unroll
    for (int o = 16; o > 0; o >>= 1) {
        float ta = __shfl_xor_sync(0xffffffffu, a, o);
        float tb = __shfl_xor_sync(0xffffffffu, b, o);
        a += ta;
        b += tb;
    }
}
__device__ __forceinline__ void wredsum4(float& a, float& b, float& c, float& d) {
#pragma unroll
    for (int o = 16; o > 0; o >>= 1) {
        float ta = __shfl_xor_sync(0xffffffffu, a, o);
        float tb = __shfl_xor_sync(0xffffffffu, b, o);
        float tc = __shfl_xor_sync(0xffffffffu, c, o);
        float td = __shfl_xor_sync(0xffffffffu, d, o);
        a += ta; b += tb; c += tc; d += td;
    }
}

// fast GELU, sign-free: u*(1+erf(z)) = u + |u| - |u|*poly*e   (z = u/sqrt2)
__device__ __forceinline__ float gelu_fast(float u) {
    float z = 0.70710678118654752f * u;
    float az = fabsf(z);
    float au = fabsf(u);
    float t = rcp_fast(fmaf(0.47047f, az, 1.0f));
    float poly = t * fmaf(t, fmaf(t, 0.7478556f, -0.0958798f), 0.3480242f);
    float e = ex2_fast(-az * az * 1.4426950408889634f);
    return 0.5f * fmaf(-au * poly, e, u + au);
}

// ============================================================================
// K1: P,Q = x @ W_top (+b1), x @ W_bot.  16-node tile, 128 threads (best-measured).
// ============================================================================
__global__ __launch_bounds__(128) void k_pq(const float* __restrict__ x,
                                            const float* __restrict__ w,   // [128,256]
                                            const float* __restrict__ b1,  // [256]
                                            int N) {
    __shared__ float xs[16][64];
    const int t = threadIdx.x;
    const int n0 = blockIdx.x * 16;

    {
        float4* xs4 = reinterpret_cast<float4*>(&xs[0][0]);
        const float4* x4 = reinterpret_cast<const float4*>(x);
#pragma unroll
        for (int i = t; i < 256; i += 128) {
            int node = n0 + (i >> 4);
            float4 v = make_float4(0.f, 0.f, 0.f, 0.f);
            if (node < N) v = x4[(size_t)node * 16 + (i & 15)];
            xs4[i] = v;
        }
    }
    __syncthreads();

    float aP0[16], aP1[16], aQ0[16], aQ1[16];
#pragma unroll
    for (int m = 0; m < 16; m++) { aP0[m] = 0.f; aP1[m] = 0.f; aQ0[m] = 0.f; aQ1[m] = 0.f; }

    const int c0 = t, c1 = t + 128;
#pragma unroll 2
    for (int k4 = 0; k4 < 16; k4++) {
        float wp0[4], wp1[4], wq0[4], wq1[4];
#pragma unroll
        for (int j = 0; j < 4; j++) {
            int k = k4 * 4 + j;
            wp0[j] = w[k * 256 + c0];
            wp1[j] = w[k * 256 + c1];
            wq0[j] = w[(64 + k) * 256 + c0];
            wq1[j] = w[(64 + k) * 256 + c1];
        }
#pragma unroll
        for (int m = 0; m < 16; m++) {
            float4 xv = *reinterpret_cast<const float4*>(&xs[m][k4 * 4]);
            float xa[4] = {xv.x, xv.y, xv.z, xv.w};
#pragma unroll
            for (int j = 0; j < 4; j++) {
                aP0[m] = fmaf(xa[j], wp0[j], aP0[m]);
                aP1[m] = fmaf(xa[j], wp1[j], aP1[m]);
                aQ0[m] = fmaf(xa[j], wq0[j], aQ0[m]);
                aQ1[m] = fmaf(xa[j], wq1[j], aQ1[m]);
            }
        }
    }

    const float bb0 = b1[c0], bb1 = b1[c1];
#pragma unroll
    for (int m = 0; m < 16; m++) {
        int n = n0 + m;
        if (n >= N) break;
        g_P[(size_t)n * 256 + c0] = aP0[m] + bb0;
        g_P[(size_t)n * 256 + c1] = aP1[m] + bb1;
        g_Q[(size_t)n * 256 + c0] = aQ0[m];
        g_Q[(size_t)n * 256 + c1] = aQ1[m];
    }
}

// ============================================================================
// Edge role: out = GELU(LN(P[row]+Q[col])) . w2 + b2  — dual-edge, f32x2,
// sign-free erf tail: z(1+erf) = (z+|z|) - (|z|*poly)*e
// ============================================================================
__device__ __forceinline__ void edge_role(int eb, const int* __restrict__ ei, int E,
                                          const float* __restrict__ gm,
                                          const float* __restrict__ bt,
                                          const float* __restrict__ w2,
                                          const float* __restrict__ b2p,
                                          float* __restrict__ out) {
    const int t = threadIdx.x;
    const int lane = t & 31;
    const int wid = t >> 5;

    long e0 = ((long)eb * 4 + wid) * EPW;
    if (e0 >= E) return;
    const int nE = (int)(E - e0 < EPW ? E - e0 : EPW);

    const float4* gmv = reinterpret_cast<const float4*>(gm);
    const float4* btv = reinterpret_cast<const float4*>(bt);
    const float4* w2v = reinterpret_cast<const float4*>(w2);
    float4 rga = gmv[lane], rgb = gmv[32 + lane];
    float4 rba = btv[lane], rbb = btv[32 + lane];
    float4 rwa = w2v[lane], rwb = w2v[32 + lane];

    const float RS2 = 0.70710678118654752f;
    u64 g2[4] = {f2pack(rga.x * RS2, rga.y * RS2), f2pack(rga.z * RS2, rga.w * RS2),
                 f2pack(rgb.x * RS2, rgb.y * RS2), f2pack(rgb.z * RS2, rgb.w * RS2)};
    u64 be2[4] = {f2pack(rba.x * RS2, rba.y * RS2), f2pack(rba.z * RS2, rba.w * RS2),
                  f2pack(rbb.x * RS2, rbb.y * RS2), f2pack(rbb.z * RS2, rbb.w * RS2)};
    u64 hw2[4] = {f2pack(rwa.x * RS2, rwa.y * RS2), f2pack(rwa.z * RS2, rwa.w * RS2),
                  f2pack(rwb.x * RS2, rwb.y * RS2), f2pack(rwb.z * RS2, rwb.w * RS2)};

    const u64 ONE2 = dup2(1.0f);
    const u64 PC = dup2(0.47047f);
    const u64 C3 = dup2(-0.7478556f);
    const u64 C2C = dup2(0.0958798f);
    const u64 C1 = dup2(-0.3480242f);
    const u64 NL2E = dup2(-1.4426950408889634f);
    const u64 AMASK = 0x7FFFFFFF7FFFFFFFull;

    const float b2 = __ldg(b2p);

    const ulonglong2* P2v = reinterpret_cast<const ulonglong2*>(g_P);
    const ulonglong2* Q2v = reinterpret_cast<const ulonglong2*>(g_Q);

    const int li = lane & 15;
    int idx = 0;
    if (li < nE) idx = ei[(lane < 16 ? e0 + li : (long)E + e0 + li)];

    for (int i = 0; i < nE; i += 2) {
        const int i2 = (i + 1 < nE) ? i + 1 : i;
        int rA = __shfl_sync(0xffffffffu, idx, i);
        int cA = __shfl_sync(0xffffffffu, idx, 16 + i);
        int rB = __shfl_sync(0xffffffffu, idx, i2);
        int cB = __shfl_sync(0xffffffffu, idx, 16 + i2);

        ulonglong2 paA = P2v[(size_t)rA * 64 + lane];
        ulonglong2 pbA = P2v[(size_t)rA * 64 + 32 + lane];
        ulonglong2 qaA = Q2v[(size_t)cA * 64 + lane];
        ulonglong2 qbA = Q2v[(size_t)cA * 64 + 32 + lane];
        ulonglong2 paB = P2v[(size_t)rB * 64 + lane];
        ulonglong2 pbB = P2v[(size_t)rB * 64 + 32 + lane];
        ulonglong2 qaB = Q2v[(size_t)cB * 64 + lane];
        ulonglong2 qbB = Q2v[(size_t)cB * 64 + 32 + lane];

        u64 sA[4], sB[4];
        sA[0] = add2(paA.x, qaA.x);
        sA[1] = add2(paA.y, qaA.y);
        sA[2] = add2(pbA.x, qbA.x);
        sA[3] = add2(pbA.y, qbA.y);
        sB[0] = add2(paB.x, qaB.x);
        sB[1] = add2(paB.y, qaB.y);
        sB[2] = add2(pbB.x, qbB.x);
        sB[3] = add2(pbB.y, qbB.y);

        u64 sumA2 = add2(add2(sA[0], sA[1]), add2(sA[2], sA[3]));
        u64 sqA2 = fma2(sA[0], sA[0], fma2(sA[1], sA[1], fma2(sA[2], sA[2], mul2(sA[3], sA[3]))));
        u64 sumB2 = add2(add2(sB[0], sB[1]), add2(sB[2], sB[3]));
        u64 sqB2 = fma2(sB[0], sB[0], fma2(sB[1], sB[1], fma2(sB[2], sB[2], mul2(sB[3], sB[3]))));

        float xl, xh;
        f2unpack(sumA2, xl, xh);
        float sumA = xl + xh;
        f2unpack(sqA2, xl, xh);
        float sqA = xl + xh;
        f2unpack(sumB2, xl, xh);
        float sumB = xl + xh;
        f2unpack(sqB2, xl, xh);
        float sqB = xl + xh;

        wredsum4(sumA, sqA, sumB, sqB);

        float meanA = sumA * (1.f / 256.f);
        float varA = sqA * (1.f / 256.f) - meanA * meanA;
        float rstdA = rsqrtf(varA + EPS_LN);
        float meanB = sumB * (1.f / 256.f);
        float varB = sqB * (1.f / 256.f) - meanB * meanB;
        float rstdB = rsqrtf(varB + EPS_LN);

        u64 A2a = dup2(rstdA), Cca = dup2(-meanA * rstdA);
        u64 A2b = dup2(rstdB), Ccb = dup2(-meanB * rstdB);

        u64 accA = 0, accB = 0;
#pragma unroll
        for (int p = 0; p < 4; p++) {
            u64 uA = fma2(sA[p], A2a, Cca);
            u64 uB = fma2(sB[p], A2b, Ccb);
            u64 zA = fma2(uA, g2[p], be2[p]);
            u64 zB = fma2(uB, g2[p], be2[p]);
            u64 azA = zA & AMASK;
            u64 azB = zB & AMASK;
            u64 dA = fma2(azA, PC, ONE2);
            u64 dB = fma2(azB, PC, ONE2);
            float dAl, dAh, dBl, dBh;
            f2unpack(dA, dAl, dAh);
            f2unpack(dB, dBl, dBh);
            u64 tA = f2pack(rcp_fast(dAl), rcp_fast(dAh));
            u64 tB = f2pack(rcp_fast(dBl), rcp_fast(dBh));
            u64 pA = fma2(tA, C3, C2C);
            u64 pB = fma2(tB, C3, C2C);
            pA = fma2(tA, pA, C1);
            pB = fma2(tB, pB, C1);
            pA = mul2(pA, tA);               // -poly (negated coeffs)
            pB = mul2(pB, tB);
            u64 zzA = mul2(azA, azA);
            u64 zzB = mul2(azB, azB);
            u64 mA = mul2(zzA, NL2E);
            u64 mB = mul2(zzB, NL2E);
            float mAl, mAh, mBl, mBh;
            f2unpack(mA, mAl, mAh);
            f2unpack(mB, mBl, mBh);
            u64 eA = f2pack(ex2_fast(mAl), ex2_fast(mAh));
            u64 eB = f2pack(ex2_fast(mBl), ex2_fast(mBh));
            // z*(1+erf(z)) = (z+|z|) + (|z|*(-poly))*e   [sign-free]
            u64 zpazA = add2(zA, azA);
            u64 zpazB = add2(zB, azB);
            u64 wA = mul2(azA, pA);
            u64 wB = mul2(azB, pB);
            u64 termA = fma2(wA, eA, zpazA);
            u64 termB = fma2(wB, eB, zpazB);
            accA = fma2(termA, hw2[p], accA);
            accB = fma2(termB, hw2[p], accB);
        }
        float aAl, aAh, aBl, aBh;
        f2unpack(accA, aAl, aAh);
        f2unpack(accB, aBl, aBh);
        float fA = aAl + aAh, fB = aBl + aBh;
        wredsum2(fA, fB);
        if (lane == 0) {
            out[e0 + i] = fA + b2;
            if (i + 1 < nE) out[e0 + i + 1] = fB + b2;
        }
    }
}

// ============================================================================
// fr role: x[64] -> Linear(128) -> LN -> GELU -> Linear(64)
// GEMM1 in node-pair f32x2 (transposed xs); LN/GELU/GEMM2 scalar.
// ============================================================================
__device__ __forceinline__ void fr_role(int nb, char* smem_raw,
                                        const float* __restrict__ x,
                                        const float* __restrict__ w1,
                                        const float* __restrict__ b1,
                                        const float* __restrict__ gm,
                                        const float* __restrict__ bt,
                                        const float* __restrict__ w2,
                                        const float* __restrict__ b2,
                                        float* __restrict__ out, int N) {
    const int t = threadIdx.x;
    const int g = t >> 6;
    const int t64 = t & 63;
    float (*xs)[16] = reinterpret_cast<float (*)[16]>(smem_raw + g * 4096);   // [64][16]
    float (*hs)[128] = reinterpret_cast<float (*)[128]>(smem_raw + 8192 + g * 8192);
    const int n0 = nb * 32 + g * 16;

    {
        const float4* x4 = reinterpret_cast<const float4*>(x);
#pragma unroll
        for (int i = t64; i < 256; i += 64) {
            int node = i >> 4, kq = i & 15;
            float4 v = make_float4(0.f, 0.f, 0.f, 0.f);
            if (n0 + node < N) v = x4[(size_t)(n0 + node) * 16 + kq];
            xs[kq * 4 + 0][node] = v.x;
            xs[kq * 4 + 1][node] = v.y;
            xs[kq * 4 + 2][node] = v.z;
            xs[kq * 4 + 3][node] = v.w;
        }
    }
    __syncthreads();

    // GEMM1: node-pair f32x2, cols c0=t64, c1=t64+64
    {
        u64 a0[8], a1[8];
#pragma unroll
        for (int p = 0; p < 8; p++) { a0[p] = 0; a1[p] = 0; }
        const int c0 = t64, c1 = t64 + 64;
#pragma unroll 4
        for (int k = 0; k < 64; k++) {
            u64 w0 = dup2(w1[k * 128 + c0]);
            u64 wB = dup2(w1[k * 128 + c1]);
#pragma unroll
            for (int p = 0; p < 8; p++) {
                u64 xv = *reinterpret_cast<const u64*>(&xs[k][2 * p]);
                a0[p] = fma2(xv, w0, a0[p]);
                a1[p] = fma2(xv, wB, a1[p]);
            }
        }
        float bb0 = b1[c0], bb1 = b1[c1];
#pragma unroll
        for (int p = 0; p < 8; p++) {
            float lo, hi;
            f2unpack(a0[p], lo, hi);
            hs[2 * p][c0] = lo + bb0;
            hs[2 * p + 1][c0] = hi + bb0;
            f2unpack(a1[p], lo, hi);
            hs[2 * p][c1] = lo + bb1;
            hs[2 * p + 1][c1] = hi + bb1;
        }
    }
    __syncthreads();

    {
        const int w2i = t64 >> 5, lane = t & 31;
        float rg[4], rb[4];
#pragma unroll
        for (int q = 0; q < 4; q++) { rg[q] = gm[lane + 32 * q]; rb[q] = bt[lane + 32 * q]; }
        for (int mm = 0; mm < 8; mm++) {
            int m = w2i * 8 + mm;
            float v[4];
            float sum = 0.f, sq = 0.f;
#pragma unroll
            for (int q = 0; q < 4; q++) {
                v[q] = hs[m][lane + 32 * q];
                sum += v[q];
                sq = fmaf(v[q], v[q], sq);
            }
            wredsum2(sum, sq);
            float mean = sum * (1.f / 128.f);
            float var = sq * (1.f / 128.f) - mean * mean;
            float rstd = rsqrtf(var + EPS_LN);
#pragma unroll
            for (int q = 0; q < 4; q++) {
                float u = fmaf((v[q] - mean) * rstd, rg[q], rb[q]);
                hs[m][lane + 32 * q] = gelu_fast(u);
            }
        }
    }
    __syncthreads();

    {
        const int mg = t64 >> 5;
        const int o0 = (t & 31) * 2;
        float acc[8][2];
#pragma unroll
        for (int mm = 0; mm < 8; mm++) { acc[mm][0] = 0.f; acc[mm][1] = 0.f; }
#pragma unroll 2
        for (int j4 = 0; j4 < 32; j4++) {
            float2 wv[4];
#pragma unroll
            for (int j = 0; j < 4; j++)
                wv[j] = *reinterpret_cast<const float2*>(&w2[(j4 * 4 + j) * 64 + o0]);
#pragma unroll
            for (int mm = 0; mm < 8; mm++) {
                int m = mg * 8 + mm;
                float4 gv = *reinterpret_cast<const float4*>(&hs[m][j4 * 4]);
                acc[mm][0] = fmaf(gv.x, wv[0].x, acc[mm][0]);
                acc[mm][0] = fmaf(gv.y, wv[1].x, acc[mm][0]);
                acc[mm][0] = fmaf(gv.z, wv[2].x, acc[mm][0]);
                acc[mm][0] = fmaf(gv.w, wv[3].x, acc[mm][0]);
                acc[mm][1] = fmaf(gv.x, wv[0].y, acc[mm][1]);
                acc[mm][1] = fmaf(gv.y, wv[1].y, acc[mm][1]);
                acc[mm][1] = fmaf(gv.z, wv[2].y, acc[mm][1]);
                acc[mm][1] = fmaf(gv.w, wv[3].y, acc[mm][1]);
            }
        }
        float bo0 = b2[o0], bo1 = b2[o0 + 1];
#pragma unroll
        for (int mm = 0; mm < 8; mm++) {
            int n = n0 + mg * 8 + mm;
            if (n < N) {
                out[(size_t)n * 64 + o0] = acc[mm][0] + bo0;
                out[(size_t)n * 64 + o0 + 1] = acc[mm][1] + bo1;
            }
        }
    }
}

// ============================================================================
// ph role: x[64] -> Linear(256) -> LN -> GELU -> Linear(128)
// GEMM1 in node-pair f32x2 (transposed xs); LN/GELU/GEMM2 scalar.
// ============================================================================
__device__ __forceinline__ void ph_role(int nb, char* smem_raw,
                                        const float* __restrict__ x,
                                        const float* __restrict__ w1,
                                        const float* __restrict__ b1,
                                        const float* __restrict__ gm,
                                        const float* __restrict__ bt,
                                        const float* __restrict__ w2,
                                        const float* __restrict__ b2,
                                        float* __restrict__ out, int N) {
    const int t = threadIdx.x;
    const int g = t >> 6;
    const int t64 = t & 63;
    float (*xs)[8] = reinterpret_cast<float (*)[8]>(smem_raw + g * 2048);     // [64][8]
    float (*hs)[256] = reinterpret_cast<float (*)[256]>(smem_raw + 4096 + g * 8192);
    const int n0 = nb * 16 + g * 8;

    {
        const float4* x4 = reinterpret_cast<const float4*>(x);
#pragma unroll
        for (int i = t64; i < 128; i += 64) {
            int node = i >> 4, kq = i & 15;
            float4 v = make_float4(0.f, 0.f, 0.f, 0.f);
            if (n0 + node < N) v = x4[(size_t)(n0 + node) * 16 + kq];
            xs[kq * 4 + 0][node] = v.x;
            xs[kq * 4 + 1][node] = v.y;
            xs[kq * 4 + 2][node] = v.z;
            xs[kq * 4 + 3][node] = v.w;
        }
    }
    __syncthreads();

    // GEMM1: node-pair f32x2, 4 cols/thread
    {
        u64 a[4][4];
#pragma unroll
        for (int cc = 0; cc < 4; cc++)
#pragma unroll
            for (int p = 0; p < 4; p++) a[cc][p] = 0;

#pragma unroll 4
        for (int k = 0; k < 64; k++) {
            u64 wr[4];
#pragma unroll
            for (int cc = 0; cc < 4; cc++)
                wr[cc] = dup2(w1[k * 256 + t64 + 64 * cc]);
#pragma unroll
            for (int p = 0; p < 4; p++) {
                u64 xv = *reinterpret_cast<const u64*>(&xs[k][2 * p]);
#pragma unroll
                for (int cc = 0; cc < 4; cc++) a[cc][p] = fma2(xv, wr[cc], a[cc][p]);
            }
        }
#pragma unroll
        for (int cc = 0; cc < 4; cc++) {
            float bb = b1[t64 + 64 * cc];
#pragma unroll
            for (int p = 0; p < 4; p++) {
                float lo, hi;
                f2unpack(a[cc][p], lo, hi);
                hs[2 * p][t64 + 64 * cc] = lo + bb;
                hs[2 * p + 1][t64 + 64 * cc] = hi + bb;
            }
        }
    }
    __syncthreads();

    {
        const int w2i = t64 >> 5, lane = t & 31;
        float rg[8], rb[8];
#pragma unroll
        for (int q = 0; q < 8; q++) { rg[q] = gm[lane + 32 * q]; rb[q] = bt[lane + 32 * q]; }
        for (int mm = 0; mm < 4; mm++) {
            int m = w2i * 4 + mm;
            float v[8];
            float sum = 0.f, sq = 0.f;
#pragma unroll
            for (int q = 0; q < 8; q++) {
                v[q] = hs[m][lane + 32 * q];
                sum += v[q];
                sq = fmaf(v[q], v[q], sq);
            }
            wredsum2(sum, sq);
            float mean = sum * (1.f / 256.f);
            float var = sq * (1.f / 256.f) - mean * mean;
            float rstd = rsqrtf(var + EPS_LN);
#pragma unroll
            for (int q = 0; q < 8; q++) {
                float u = fmaf((v[q] - mean) * rstd, rg[q], rb[q]);
                hs[m][lane + 32 * q] = gelu_fast(u);
            }
        }
    }
    __syncthreads();

    {
        const int mg = t64 >> 5;
        const int o0 = (t & 31) * 4;
        float acc[4][4];
#pragma unroll
        for (int mm = 0; mm < 4; mm++)
#pragma unroll
            for (int oo = 0; oo < 4; oo++) acc[mm][oo] = 0.f;

#pragma unroll 2
        for (int j4 = 0; j4 < 64; j4++) {
            float4 wv[4];
#pragma unroll
            for (int j = 0; j < 4; j++)
                wv[j] = *reinterpret_cast<const float4*>(&w2[(j4 * 4 + j) * 128 + o0]);
#pragma unroll
            for (int mm = 0; mm < 4; mm++) {
                int m = mg * 4 + mm;
                float4 gv = *reinterpret_cast<const float4*>(&hs[m][j4 * 4]);
                float gvals[4] = {gv.x, gv.y, gv.z, gv.w};
#pragma unroll
                for (int j = 0; j < 4; j++) {
                    acc[mm][0] = fmaf(gvals[j], wv[j].x, acc[mm][0]);
                    acc[mm][1] = fmaf(gvals[j], wv[j].y, acc[mm][1]);
                    acc[mm][2] = fmaf(gvals[j], wv[j].z, acc[mm][2]);
                    acc[mm][3] = fmaf(gvals[j], wv[j].w, acc[mm][3]);
                }
            }
        }
        float4 bo = *reinterpret_cast<const float4*>(&b2[o0]);
#pragma unroll
        for (int mm = 0; mm < 4; mm++) {
            int n = n0 + mg * 4 + mm;
            if (n < N) {
                float4 rr;
                rr.x = acc[mm][0] + bo.x;
                rr.y = acc[mm][1] + bo.y;
                rr.z = acc[mm][2] + bo.z;
                rr.w = acc[mm][3] + bo.w;
                *reinterpret_cast<float4*>(&out[(size_t)n * 128 + o0]) = rr;
            }
        }
    }
}

// ============================================================================
// Mega kernel: role-interleaved edge + fr + ph (8:3 block pattern), occ 6
// ============================================================================
__global__ __launch_bounds__(128, 6) void k_mega(
    const float* __restrict__ x, const int* __restrict__ ei, int N, int E,
    const float* __restrict__ fr_w1, const float* __restrict__ fr_b1,
    const float* __restrict__ fr_g, const float* __restrict__ fr_be,
    const float* __restrict__ fr_w2, const float* __restrict__ fr_b2,
    const float* __restrict__ ph_w1, const float* __restrict__ ph_b1,
    const float* __restrict__ ph_g, const float* __restrict__ ph_be,
    const float* __restrict__ ph_w2, const float* __restrict__ ph_b2,
    const float* __restrict__ sp_g, const float* __restrict__ sp_be,
    const float* __restrict__ sp_w2, const float* __restrict__ sp_b2,
    float* __restrict__ out_sp, float* __restrict__ out_fr, float* __restrict__ out_ph,
    int nfr, int nph) {
    __shared__ __align__(16) char smem_raw[24576];
    const int b = blockIdx.x;
    const int gid = b / 11;
    const int slot = b - gid * 11;

    if (slot < 8) {
        edge_role(gid * 8 + slot, ei, E, sp_g, sp_be, sp_w2, sp_b2, out_sp);
    } else {
        int nb = gid * 3 + (slot - 8);
        if (nb < nfr) {
            fr_role(nb, smem_raw, x, fr_w1, fr_b1, fr_g, fr_be, fr_w2, fr_b2, out_fr, N);
        } else if (nb < nfr + nph) {
            ph_role(nb - nfr, smem_raw, x, ph_w1, ph_b1, ph_g, ph_be, ph_w2, ph_b2, out_ph, N);
        }
    }
}

// ============================================================================
// launch
// ============================================================================
extern "C" void kernel_launch(void* const* d_in, const int* in_sizes, int n_in,
                              void* d_out, int out_size) {
    const float* x = (const float*)d_in[0];
    const int* ei = (const int*)d_in[1];
    const float* sp_w1 = (const float*)d_in[2];
    const float* sp_b1 = (const float*)d_in[3];
    const float* sp_g = (const float*)d_in[4];
    const float* sp_be = (const float*)d_in[5];
    const float* sp_w2 = (const float*)d_in[6];
    const float* sp_b2 = (const float*)d_in[7];
    const float* fr_w1 = (const float*)d_in[8];
    const float* fr_b1 = (const float*)d_in[9];
    const float* fr_g = (const float*)d_in[10];
    const float* fr_be = (const float*)d_in[11];
    const float* fr_w2 = (const float*)d_in[12];
    const float* fr_b2 = (const float*)d_in[13];
    const float* ph_w1 = (const float*)d_in[14];
    const float* ph_b1 = (const float*)d_in[15];
    const float* ph_g = (const float*)d_in[16];
    const float* ph_be = (const float*)d_in[17];
    const float* ph_w2 = (const float*)d_in[18];
    const float* ph_b2 = (const float*)d_in[19];

    const int N = in_sizes[0] / 64;
    const int E = in_sizes[1] / 2;

    float* out_sp = (float*)d_out;             // [E]
    float* out_fr = out_sp + (size_t)E;        // [N,64]
    float* out_ph = out_fr + (size_t)N * 64;   // [N,128]

    // Phase 1: P/Q precompute (edge branch depends on it) — 16-node tile
    k_pq<<<(N + 15) / 16, 128>>>(x, sp_w1, sp_b1, N);

    // Phase 2: role-interleaved mega kernel
    const int nfr = (N + 31) / 32;
    const int nph = (N + 15) / 16;
    const int node_blocks = nfr + nph;
    const long ewarps = ((long)E + EPW - 1) / EPW;
    const int eblk = (int)((ewarps + 3) / 4);
    int Ga = (node_blocks + 2) / 3;
    int Gb = (eblk + 7) / 8;
    int G = Ga > Gb ? Ga : Gb;

    k_mega<<<G * 11, 128>>>(x, ei, N, E,
                            fr_w1, fr_b1, fr_g, fr_be, fr_w2, fr_b2,
                            ph_w1, ph_b1, ph_g, ph_be, ph_w2, ph_b2,
                            sp_g, sp_be, sp_w2, sp_b2,
                            out_sp, out_fr, out_ph, nfr, nph);
}

// round 16
// speedup vs baseline: 1.0482x; 1.0018x over previous
#include <cuda_runtime.h>
#include <stdint.h>
#include <math.h>

#define NMAX 50000
#define EPS_LN 1e-5f
#define EPW 16

typedef unsigned long long u64;

// Scratch: P = x @ sp_w1[0:64,:] + sp_b1, Q = x @ sp_w1[64:128,:]   (each [N,256])
__device__ float g_P[(size_t)NMAX * 256];
__device__ float g_Q[(size_t)NMAX * 256];

// ---------------- f32x2 packed helpers ----------------
__device__ __forceinline__ u64 f2pack(float lo, float hi) {
    u64 r; asm("mov.b64 %0, {%1, %2};" : "=l"(r) : "f"(lo), "f"(hi)); return r;
}
__device__ __forceinline__ void f2unpack(u64 v, float& lo, float& hi) {
    asm("mov.b64 {%0, %1}, %2;" : "=f"(lo), "=f"(hi) : "l"(v));
}
__device__ __forceinline__ u64 dup2(float v) { return f2pack(v, v); }
__device__ __forceinline__ u64 fma2(u64 a, u64 b, u64 c) {
    u64 d; asm("fma.rn.f32x2 %0, %1, %2, %3;" : "=l"(d) : "l"(a), "l"(b), "l"(c)); return d;
}
__device__ __forceinline__ u64 add2(u64 a, u64 b) {
    u64 d; asm("add.rn.f32x2 %0, %1, %2;" : "=l"(d) : "l"(a), "l"(b)); return d;
}
__device__ __forceinline__ u64 mul2(u64 a, u64 b) {
    u64 d; asm("mul.rn.f32x2 %0, %1, %2;" : "=l"(d) : "l"(a), "l"(b)); return d;
}
__device__ __forceinline__ float rcp_fast(float x) {
    float r; asm("rcp.approx.f32 %0, %1;" : "=f"(r) : "f"(x)); return r;
}
__device__ __forceinline__ float ex2_fast(float x) {
    float r; asm("ex2.approx.f32 %0, %1;" : "=f"(r) : "f"(x)); return r;
}

__device__ __forceinline__ float wredsum(float v) {
#pragma unroll
    for (int o = 16; o > 0; o >>= 1) v += __shfl_xor_sync(0xffffffffu, v, o);
    return v;
}
__device__ __forceinline__ void wredsum2(float& a, float& b) {
#pragma unroll
    for (int o = 16; o > 0; o >>= 1) {
        float ta = __shfl_xor_sync(0xffffffffu, a, o);
        float tb = __shfl_xor_sync(0xffffffffu, b, o);
        a += ta;
        b += tb;
    }
}
__device__ __forceinline__ void wredsum4(float& a, float& b, float& c, float& d) {
#pragma unroll
    for (int o = 16; o > 0; o >>= 1) {
        float ta = __shfl_xor_sync(0xffffffffu, a, o);
        float tb = __shfl_xor_sync(0xffffffffu, b, o);
        float tc = __shfl_xor_sync(0xffffffffu, c, o);
        float td = __shfl_xor_sync(0xffffffffu, d, o);
        a += ta; b += tb; c += tc; d += td;
    }
}

// fast GELU, sign-free: u*(1+erf(z)) = u + |u| - |u|*poly*e   (z = u/sqrt2)
__device__ __forceinline__ float gelu_fast(float u) {
    float z = 0.70710678118654752f * u;
    float az = fabsf(z);
    float au = fabsf(u);
    float t = rcp_fast(fmaf(0.47047f, az, 1.0f));
    float poly = t * fmaf(t, fmaf(t, 0.7478556f, -0.0958798f), 0.3480242f);
    float e = ex2_fast(-az * az * 1.4426950408889634f);
    return 0.5f * fmaf(-au * poly, e, u + au);
}

// ============================================================================
// K1: P,Q = x @ W_top (+b1), x @ W_bot.  16-node tile, 128 threads (best-measured).
// ============================================================================
__global__ __launch_bounds__(128) void k_pq(const float* __restrict__ x,
                                            const float* __restrict__ w,   // [128,256]
                                            const float* __restrict__ b1,  // [256]
                                            int N) {
    __shared__ float xs[16][64];
    const int t = threadIdx.x;
    const int n0 = blockIdx.x * 16;

    {
        float4* xs4 = reinterpret_cast<float4*>(&xs[0][0]);
        const float4* x4 = reinterpret_cast<const float4*>(x);
#pragma unroll
        for (int i = t; i < 256; i += 128) {
            int node = n0 + (i >> 4);
            float4 v = make_float4(0.f, 0.f, 0.f, 0.f);
            if (node < N) v = x4[(size_t)node * 16 + (i & 15)];
            xs4[i] = v;
        }
    }
    __syncthreads();

    float aP0[16], aP1[16], aQ0[16], aQ1[16];
#pragma unroll
    for (int m = 0; m < 16; m++) { aP0[m] = 0.f; aP1[m] = 0.f; aQ0[m] = 0.f; aQ1[m] = 0.f; }

    const int c0 = t, c1 = t + 128;
#pragma unroll 2
    for (int k4 = 0; k4 < 16; k4++) {
        float wp0[4], wp1[4], wq0[4], wq1[4];
#pragma unroll
        for (int j = 0; j < 4; j++) {
            int k = k4 * 4 + j;
            wp0[j] = w[k * 256 + c0];
            wp1[j] = w[k * 256 + c1];
            wq0[j] = w[(64 + k) * 256 + c0];
            wq1[j] = w[(64 + k) * 256 + c1];
        }
#pragma unroll
        for (int m = 0; m < 16; m++) {
            float4 xv = *reinterpret_cast<const float4*>(&xs[m][k4 * 4]);
            float xa[4] = {xv.x, xv.y, xv.z, xv.w};
#pragma unroll
            for (int j = 0; j < 4; j++) {
                aP0[m] = fmaf(xa[j], wp0[j], aP0[m]);
                aP1[m] = fmaf(xa[j], wp1[j], aP1[m]);
                aQ0[m] = fmaf(xa[j], wq0[j], aQ0[m]);
                aQ1[m] = fmaf(xa[j], wq1[j], aQ1[m]);
            }
        }
    }

    const float bb0 = b1[c0], bb1 = b1[c1];
#pragma unroll
    for (int m = 0; m < 16; m++) {
        int n = n0 + m;
        if (n >= N) break;
        g_P[(size_t)n * 256 + c0] = aP0[m] + bb0;
        g_P[(size_t)n * 256 + c1] = aP1[m] + bb1;
        g_Q[(size_t)n * 256 + c0] = aQ0[m];
        g_Q[(size_t)n * 256 + c1] = aQ1[m];
    }
}

// ============================================================================
// Edge role: out = GELU(LN(P[row]+Q[col])) . w2 + b2  — dual-edge, f32x2,
// sign-free erf tail: z(1+erf) = (z+|z|) - (|z|*poly)*e
// ============================================================================
__device__ __forceinline__ void edge_role(int eb, const int* __restrict__ ei, int E,
                                          const float* __restrict__ gm,
                                          const float* __restrict__ bt,
                                          const float* __restrict__ w2,
                                          const float* __restrict__ b2p,
                                          float* __restrict__ out) {
    const int t = threadIdx.x;
    const int lane = t & 31;
    const int wid = t >> 5;

    long e0 = ((long)eb * 4 + wid) * EPW;
    if (e0 >= E) return;
    const int nE = (int)(E - e0 < EPW ? E - e0 : EPW);

    const float4* gmv = reinterpret_cast<const float4*>(gm);
    const float4* btv = reinterpret_cast<const float4*>(bt);
    const float4* w2v = reinterpret_cast<const float4*>(w2);
    float4 rga = gmv[lane], rgb = gmv[32 + lane];
    float4 rba = btv[lane], rbb = btv[32 + lane];
    float4 rwa = w2v[lane], rwb = w2v[32 + lane];

    const float RS2 = 0.70710678118654752f;
    u64 g2[4] = {f2pack(rga.x * RS2, rga.y * RS2), f2pack(rga.z * RS2, rga.w * RS2),
                 f2pack(rgb.x * RS2, rgb.y * RS2), f2pack(rgb.z * RS2, rgb.w * RS2)};
    u64 be2[4] = {f2pack(rba.x * RS2, rba.y * RS2), f2pack(rba.z * RS2, rba.w * RS2),
                  f2pack(rbb.x * RS2, rbb.y * RS2), f2pack(rbb.z * RS2, rbb.w * RS2)};
    u64 hw2[4] = {f2pack(rwa.x * RS2, rwa.y * RS2), f2pack(rwa.z * RS2, rwa.w * RS2),
                  f2pack(rwb.x * RS2, rwb.y * RS2), f2pack(rwb.z * RS2, rwb.w * RS2)};

    const u64 ONE2 = dup2(1.0f);
    const u64 PC = dup2(0.47047f);
    const u64 C3 = dup2(-0.7478556f);
    const u64 C2C = dup2(0.0958798f);
    const u64 C1 = dup2(-0.3480242f);
    const u64 NL2E = dup2(-1.4426950408889634f);
    const u64 AMASK = 0x7FFFFFFF7FFFFFFFull;

    const float b2 = __ldg(b2p);

    const ulonglong2* P2v = reinterpret_cast<const ulonglong2*>(g_P);
    const ulonglong2* Q2v = reinterpret_cast<const ulonglong2*>(g_Q);

    const int li = lane & 15;
    int idx = 0;
    if (li < nE) idx = ei[(lane < 16 ? e0 + li : (long)E + e0 + li)];

    for (int i = 0; i < nE; i += 2) {
        const int i2 = (i + 1 < nE) ? i + 1 : i;
        int rA = __shfl_sync(0xffffffffu, idx, i);
        int cA = __shfl_sync(0xffffffffu, idx, 16 + i);
        int rB = __shfl_sync(0xffffffffu, idx, i2);
        int cB = __shfl_sync(0xffffffffu, idx, 16 + i2);

        ulonglong2 paA = P2v[(size_t)rA * 64 + lane];
        ulonglong2 pbA = P2v[(size_t)rA * 64 + 32 + lane];
        ulonglong2 qaA = Q2v[(size_t)cA * 64 + lane];
        ulonglong2 qbA = Q2v[(size_t)cA * 64 + 32 + lane];
        ulonglong2 paB = P2v[(size_t)rB * 64 + lane];
        ulonglong2 pbB = P2v[(size_t)rB * 64 + 32 + lane];
        ulonglong2 qaB = Q2v[(size_t)cB * 64 + lane];
        ulonglong2 qbB = Q2v[(size_t)cB * 64 + 32 + lane];

        u64 sA[4], sB[4];
        sA[0] = add2(paA.x, qaA.x);
        sA[1] = add2(paA.y, qaA.y);
        sA[2] = add2(pbA.x, qbA.x);
        sA[3] = add2(pbA.y, qbA.y);
        sB[0] = add2(paB.x, qaB.x);
        sB[1] = add2(paB.y, qaB.y);
        sB[2] = add2(pbB.x, qbB.x);
        sB[3] = add2(pbB.y, qbB.y);

        u64 sumA2 = add2(add2(sA[0], sA[1]), add2(sA[2], sA[3]));
        u64 sqA2 = fma2(sA[0], sA[0], fma2(sA[1], sA[1], fma2(sA[2], sA[2], mul2(sA[3], sA[3]))));
        u64 sumB2 = add2(add2(sB[0], sB[1]), add2(sB[2], sB[3]));
        u64 sqB2 = fma2(sB[0], sB[0], fma2(sB[1], sB[1], fma2(sB[2], sB[2], mul2(sB[3], sB[3]))));

        float xl, xh;
        f2unpack(sumA2, xl, xh);
        float sumA = xl + xh;
        f2unpack(sqA2, xl, xh);
        float sqA = xl + xh;
        f2unpack(sumB2, xl, xh);
        float sumB = xl + xh;
        f2unpack(sqB2, xl, xh);
        float sqB = xl + xh;

        wredsum4(sumA, sqA, sumB, sqB);

        float meanA = sumA * (1.f / 256.f);
        float varA = sqA * (1.f / 256.f) - meanA * meanA;
        float rstdA = rsqrtf(varA + EPS_LN);
        float meanB = sumB * (1.f / 256.f);
        float varB = sqB * (1.f / 256.f) - meanB * meanB;
        float rstdB = rsqrtf(varB + EPS_LN);

        u64 A2a = dup2(rstdA), Cca = dup2(-meanA * rstdA);
        u64 A2b = dup2(rstdB), Ccb = dup2(-meanB * rstdB);

        u64 accA = 0, accB = 0;
#pragma unroll
        for (int p = 0; p < 4; p++) {
            u64 uA = fma2(sA[p], A2a, Cca);
            u64 uB = fma2(sB[p], A2b, Ccb);
            u64 zA = fma2(uA, g2[p], be2[p]);
            u64 zB = fma2(uB, g2[p], be2[p]);
            u64 azA = zA & AMASK;
            u64 azB = zB & AMASK;
            u64 dA = fma2(azA, PC, ONE2);
            u64 dB = fma2(azB, PC, ONE2);
            float dAl, dAh, dBl, dBh;
            f2unpack(dA, dAl, dAh);
            f2unpack(dB, dBl, dBh);
            u64 tA = f2pack(rcp_fast(dAl), rcp_fast(dAh));
            u64 tB = f2pack(rcp_fast(dBl), rcp_fast(dBh));
            u64 pA = fma2(tA, C3, C2C);
            u64 pB = fma2(tB, C3, C2C);
            pA = fma2(tA, pA, C1);
            pB = fma2(tB, pB, C1);
            pA = mul2(pA, tA);               // -poly (negated coeffs)
            pB = mul2(pB, tB);
            u64 zzA = mul2(azA, azA);
            u64 zzB = mul2(azB, azB);
            u64 mA = mul2(zzA, NL2E);
            u64 mB = mul2(zzB, NL2E);
            float mAl, mAh, mBl, mBh;
            f2unpack(mA, mAl, mAh);
            f2unpack(mB, mBl, mBh);
            u64 eA = f2pack(ex2_fast(mAl), ex2_fast(mAh));
            u64 eB = f2pack(ex2_fast(mBl), ex2_fast(mBh));
            // z*(1+erf(z)) = (z+|z|) + (|z|*(-poly))*e   [sign-free]
            u64 zpazA = add2(zA, azA);
            u64 zpazB = add2(zB, azB);
            u64 wA = mul2(azA, pA);
            u64 wB = mul2(azB, pB);
            u64 termA = fma2(wA, eA, zpazA);
            u64 termB = fma2(wB, eB, zpazB);
            accA = fma2(termA, hw2[p], accA);
            accB = fma2(termB, hw2[p], accB);
        }
        float aAl, aAh, aBl, aBh;
        f2unpack(accA, aAl, aAh);
        f2unpack(accB, aBl, aBh);
        float fA = aAl + aAh, fB = aBl + aBh;
        wredsum2(fA, fB);
        if (lane == 0) {
            out[e0 + i] = fA + b2;
            if (i + 1 < nE) out[e0 + i + 1] = fB + b2;
        }
    }
}

// ============================================================================
// fr role: x[64] -> Linear(128) -> LN -> GELU -> Linear(64)
// GEMM1 f32x2; LN/GELU with CONTIGUOUS lane layout (float4 LDS/STS).
// ============================================================================
__device__ __forceinline__ void fr_role(int nb, char* smem_raw,
                                        const float* __restrict__ x,
                                        const float* __restrict__ w1,
                                        const float* __restrict__ b1,
                                        const float* __restrict__ gm,
                                        const float* __restrict__ bt,
                                        const float* __restrict__ w2,
                                        const float* __restrict__ b2,
                                        float* __restrict__ out, int N) {
    const int t = threadIdx.x;
    const int g = t >> 6;
    const int t64 = t & 63;
    float (*xs)[16] = reinterpret_cast<float (*)[16]>(smem_raw + g * 4096);   // [64][16]
    float (*hs)[128] = reinterpret_cast<float (*)[128]>(smem_raw + 8192 + g * 8192);
    const int n0 = nb * 32 + g * 16;

    {
        const float4* x4 = reinterpret_cast<const float4*>(x);
#pragma unroll
        for (int i = t64; i < 256; i += 64) {
            int node = i >> 4, kq = i & 15;
            float4 v = make_float4(0.f, 0.f, 0.f, 0.f);
            if (n0 + node < N) v = x4[(size_t)(n0 + node) * 16 + kq];
            xs[kq * 4 + 0][node] = v.x;
            xs[kq * 4 + 1][node] = v.y;
            xs[kq * 4 + 2][node] = v.z;
            xs[kq * 4 + 3][node] = v.w;
        }
    }
    __syncthreads();

    // GEMM1: node-pair f32x2, cols c0=t64, c1=t64+64
    {
        u64 a0[8], a1[8];
#pragma unroll
        for (int p = 0; p < 8; p++) { a0[p] = 0; a1[p] = 0; }
        const int c0 = t64, c1 = t64 + 64;
#pragma unroll 4
        for (int k = 0; k < 64; k++) {
            u64 w0 = dup2(w1[k * 128 + c0]);
            u64 wB = dup2(w1[k * 128 + c1]);
#pragma unroll
            for (int p = 0; p < 8; p++) {
                u64 xv = *reinterpret_cast<const u64*>(&xs[k][2 * p]);
                a0[p] = fma2(xv, w0, a0[p]);
                a1[p] = fma2(xv, wB, a1[p]);
            }
        }
        float bb0 = b1[c0], bb1 = b1[c1];
#pragma unroll
        for (int p = 0; p < 8; p++) {
            float lo, hi;
            f2unpack(a0[p], lo, hi);
            hs[2 * p][c0] = lo + bb0;
            hs[2 * p + 1][c0] = hi + bb0;
            f2unpack(a1[p], lo, hi);
            hs[2 * p][c1] = lo + bb1;
            hs[2 * p + 1][c1] = hi + bb1;
        }
    }
    __syncthreads();

    // LN + GELU: contiguous lane layout — lane owns elems [4*lane, 4*lane+4)
    {
        const int w2i = t64 >> 5, lane = t & 31;
        float4 rg4 = *reinterpret_cast<const float4*>(gm + 4 * lane);
        float4 rb4 = *reinterpret_cast<const float4*>(bt + 4 * lane);
        for (int mm = 0; mm < 8; mm++) {
            int m = w2i * 8 + mm;
            float4 v4 = *reinterpret_cast<const float4*>(&hs[m][4 * lane]);
            float sum = (v4.x + v4.y) + (v4.z + v4.w);
            float sq = fmaf(v4.x, v4.x, fmaf(v4.y, v4.y, fmaf(v4.z, v4.z, v4.w * v4.w)));
            wredsum2(sum, sq);
            float mean = sum * (1.f / 128.f);
            float var = sq * (1.f / 128.f) - mean * mean;
            float rstd = rsqrtf(var + EPS_LN);
            v4.x = gelu_fast(fmaf((v4.x - mean) * rstd, rg4.x, rb4.x));
            v4.y = gelu_fast(fmaf((v4.y - mean) * rstd, rg4.y, rb4.y));
            v4.z = gelu_fast(fmaf((v4.z - mean) * rstd, rg4.z, rb4.z));
            v4.w = gelu_fast(fmaf((v4.w - mean) * rstd, rg4.w, rb4.w));
            *reinterpret_cast<float4*>(&hs[m][4 * lane]) = v4;
        }
    }
    __syncthreads();

    {
        const int mg = t64 >> 5;
        const int o0 = (t & 31) * 2;
        float acc[8][2];
#pragma unroll
        for (int mm = 0; mm < 8; mm++) { acc[mm][0] = 0.f; acc[mm][1] = 0.f; }
#pragma unroll 2
        for (int j4 = 0; j4 < 32; j4++) {
            float2 wv[4];
#pragma unroll
            for (int j = 0; j < 4; j++)
                wv[j] = *reinterpret_cast<const float2*>(&w2[(j4 * 4 + j) * 64 + o0]);
#pragma unroll
            for (int mm = 0; mm < 8; mm++) {
                int m = mg * 8 + mm;
                float4 gv = *reinterpret_cast<const float4*>(&hs[m][j4 * 4]);
                acc[mm][0] = fmaf(gv.x, wv[0].x, acc[mm][0]);
                acc[mm][0] = fmaf(gv.y, wv[1].x, acc[mm][0]);
                acc[mm][0] = fmaf(gv.z, wv[2].x, acc[mm][0]);
                acc[mm][0] = fmaf(gv.w, wv[3].x, acc[mm][0]);
                acc[mm][1] = fmaf(gv.x, wv[0].y, acc[mm][1]);
                acc[mm][1] = fmaf(gv.y, wv[1].y, acc[mm][1]);
                acc[mm][1] = fmaf(gv.z, wv[2].y, acc[mm][1]);
                acc[mm][1] = fmaf(gv.w, wv[3].y, acc[mm][1]);
            }
        }
        float bo0 = b2[o0], bo1 = b2[o0 + 1];
#pragma unroll
        for (int mm = 0; mm < 8; mm++) {
            int n = n0 + mg * 8 + mm;
            if (n < N) {
                out[(size_t)n * 64 + o0] = acc[mm][0] + bo0;
                out[(size_t)n * 64 + o0 + 1] = acc[mm][1] + bo1;
            }
        }
    }
}

// ============================================================================
// ph role: x[64] -> Linear(256) -> LN -> GELU -> Linear(128)
// GEMM1 f32x2; LN/GELU with CONTIGUOUS lane layout (2x float4 per lane).
// ============================================================================
__device__ __forceinline__ void ph_role(int nb, char* smem_raw,
                                        const float* __restrict__ x,
                                        const float* __restrict__ w1,
                                        const float* __restrict__ b1,
                                        const float* __restrict__ gm,
                                        const float* __restrict__ bt,
                                        const float* __restrict__ w2,
                                        const float* __restrict__ b2,
                                        float* __restrict__ out, int N) {
    const int t = threadIdx.x;
    const int g = t >> 6;
    const int t64 = t & 63;
    float (*xs)[8] = reinterpret_cast<float (*)[8]>(smem_raw + g * 2048);     // [64][8]
    float (*hs)[256] = reinterpret_cast<float (*)[256]>(smem_raw + 4096 + g * 8192);
    const int n0 = nb * 16 + g * 8;

    {
        const float4* x4 = reinterpret_cast<const float4*>(x);
#pragma unroll
        for (int i = t64; i < 128; i += 64) {
            int node = i >> 4, kq = i & 15;
            float4 v = make_float4(0.f, 0.f, 0.f, 0.f);
            if (n0 + node < N) v = x4[(size_t)(n0 + node) * 16 + kq];
            xs[kq * 4 + 0][node] = v.x;
            xs[kq * 4 + 1][node] = v.y;
            xs[kq * 4 + 2][node] = v.z;
            xs[kq * 4 + 3][node] = v.w;
        }
    }
    __syncthreads();

    // GEMM1: node-pair f32x2, 4 cols/thread
    {
        u64 a[4][4];
#pragma unroll
        for (int cc = 0; cc < 4; cc++)
#pragma unroll
            for (int p = 0; p < 4; p++) a[cc][p] = 0;

#pragma unroll 4
        for (int k = 0; k < 64; k++) {
            u64 wr[4];
#pragma unroll
            for (int cc = 0; cc < 4; cc++)
                wr[cc] = dup2(w1[k * 256 + t64 + 64 * cc]);
#pragma unroll
            for (int p = 0; p < 4; p++) {
                u64 xv = *reinterpret_cast<const u64*>(&xs[k][2 * p]);
#pragma unroll
                for (int cc = 0; cc < 4; cc++) a[cc][p] = fma2(xv, wr[cc], a[cc][p]);
            }
        }
#pragma unroll
        for (int cc = 0; cc < 4; cc++) {
            float bb = b1[t64 + 64 * cc];
#pragma unroll
            for (int p = 0; p < 4; p++) {
                float lo, hi;
                f2unpack(a[cc][p], lo, hi);
                hs[2 * p][t64 + 64 * cc] = lo + bb;
                hs[2 * p + 1][t64 + 64 * cc] = hi + bb;
            }
        }
    }
    __syncthreads();

    // LN + GELU: contiguous lane layout — lane owns elems [8*lane, 8*lane+8)
    {
        const int w2i = t64 >> 5, lane = t & 31;
        float4 rg4a = *reinterpret_cast<const float4*>(gm + 8 * lane);
        float4 rg4b = *reinterpret_cast<const float4*>(gm + 8 * lane + 4);
        float4 rb4a = *reinterpret_cast<const float4*>(bt + 8 * lane);
        float4 rb4b = *reinterpret_cast<const float4*>(bt + 8 * lane + 4);
        for (int mm = 0; mm < 4; mm++) {
            int m = w2i * 4 + mm;
            float4 va = *reinterpret_cast<const float4*>(&hs[m][8 * lane]);
            float4 vb = *reinterpret_cast<const float4*>(&hs[m][8 * lane + 4]);
            float sum = ((va.x + va.y) + (va.z + va.w)) + ((vb.x + vb.y) + (vb.z + vb.w));
            float sq = fmaf(va.x, va.x, fmaf(va.y, va.y, fmaf(va.z, va.z, va.w * va.w)));
            sq = fmaf(vb.x, vb.x, fmaf(vb.y, vb.y, fmaf(vb.z, vb.z, fmaf(vb.w, vb.w, sq))));
            wredsum2(sum, sq);
            float mean = sum * (1.f / 256.f);
            float var = sq * (1.f / 256.f) - mean * mean;
            float rstd = rsqrtf(var + EPS_LN);
            va.x = gelu_fast(fmaf((va.x - mean) * rstd, rg4a.x, rb4a.x));
            va.y = gelu_fast(fmaf((va.y - mean) * rstd, rg4a.y, rb4a.y));
            va.z = gelu_fast(fmaf((va.z - mean) * rstd, rg4a.z, rb4a.z));
            va.w = gelu_fast(fmaf((va.w - mean) * rstd, rg4a.w, rb4a.w));
            vb.x = gelu_fast(fmaf((vb.x - mean) * rstd, rg4b.x, rb4b.x));
            vb.y = gelu_fast(fmaf((vb.y - mean) * rstd, rg4b.y, rb4b.y));
            vb.z = gelu_fast(fmaf((vb.z - mean) * rstd, rg4b.z, rb4b.z));
            vb.w = gelu_fast(fmaf((vb.w - mean) * rstd, rg4b.w, rb4b.w));
            *reinterpret_cast<float4*>(&hs[m][8 * lane]) = va;
            *reinterpret_cast<float4*>(&hs[m][8 * lane + 4]) = vb;
        }
    }
    __syncthreads();

    {
        const int mg = t64 >> 5;
        const int o0 = (t & 31) * 4;
        float acc[4][4];
#pragma unroll
        for (int mm = 0; mm < 4; mm++)
#pragma unroll
            for (int oo = 0; oo < 4; oo++) acc[mm][oo] = 0.f;

#pragma unroll 2
        for (int j4 = 0; j4 < 64; j4++) {
            float4 wv[4];
#pragma unroll
            for (int j = 0; j < 4; j++)
                wv[j] = *reinterpret_cast<const float4*>(&w2[(j4 * 4 + j) * 128 + o0]);
#pragma unroll
            for (int mm = 0; mm < 4; mm++) {
                int m = mg * 4 + mm;
                float4 gv = *reinterpret_cast<const float4*>(&hs[m][j4 * 4]);
                float gvals[4] = {gv.x, gv.y, gv.z, gv.w};
#pragma unroll
                for (int j = 0; j < 4; j++) {
                    acc[mm][0] = fmaf(gvals[j], wv[j].x, acc[mm][0]);
                    acc[mm][1] = fmaf(gvals[j], wv[j].y, acc[mm][1]);
                    acc[mm][2] = fmaf(gvals[j], wv[j].z, acc[mm][2]);
                    acc[mm][3] = fmaf(gvals[j], wv[j].w, acc[mm][3]);
                }
            }
        }
        float4 bo = *reinterpret_cast<const float4*>(&b2[o0]);
#pragma unroll
        for (int mm = 0; mm < 4; mm++) {
            int n = n0 + mg * 4 + mm;
            if (n < N) {
                float4 rr;
                rr.x = acc[mm][0] + bo.x;
                rr.y = acc[mm][1] + bo.y;
                rr.z = acc[mm][2] + bo.z;
                rr.w = acc[mm][3] + bo.w;
                *reinterpret_cast<float4*>(&out[(size_t)n * 128 + o0]) = rr;
            }
        }
    }
}

// ============================================================================
// Mega kernel: role-interleaved edge + fr + ph (8:3 block pattern), occ 6
// ============================================================================
__global__ __launch_bounds__(128, 6) void k_mega(
    const float* __restrict__ x, const int* __restrict__ ei, int N, int E,
    const float* __restrict__ fr_w1, const float* __restrict__ fr_b1,
    const float* __restrict__ fr_g, const float* __restrict__ fr_be,
    const float* __restrict__ fr_w2, const float* __restrict__ fr_b2,
    const float* __restrict__ ph_w1, const float* __restrict__ ph_b1,
    const float* __restrict__ ph_g, const float* __restrict__ ph_be,
    const float* __restrict__ ph_w2, const float* __restrict__ ph_b2,
    const float* __restrict__ sp_g, const float* __restrict__ sp_be,
    const float* __restrict__ sp_w2, const float* __restrict__ sp_b2,
    float* __restrict__ out_sp, float* __restrict__ out_fr, float* __restrict__ out_ph,
    int nfr, int nph) {
    __shared__ __align__(16) char smem_raw[24576];
    const int b = blockIdx.x;
    const int gid = b / 11;
    const int slot = b - gid * 11;

    if (slot < 8) {
        edge_role(gid * 8 + slot, ei, E, sp_g, sp_be, sp_w2, sp_b2, out_sp);
    } else {
        int nb = gid * 3 + (slot - 8);
        if (nb < nfr) {
            fr_role(nb, smem_raw, x, fr_w1, fr_b1, fr_g, fr_be, fr_w2, fr_b2, out_fr, N);
        } else if (nb < nfr + nph) {
            ph_role(nb - nfr, smem_raw, x, ph_w1, ph_b1, ph_g, ph_be, ph_w2, ph_b2, out_ph, N);
        }
    }
}

// ============================================================================
// launch
// ============================================================================
extern "C" void kernel_launch(void* const* d_in, const int* in_sizes, int n_in,
                              void* d_out, int out_size) {
    const float* x = (const float*)d_in[0];
    const int* ei = (const int*)d_in[1];
    const float* sp_w1 = (const float*)d_in[2];
    const float* sp_b1 = (const float*)d_in[3];
    const float* sp_g = (const float*)d_in[4];
    const float* sp_be = (const float*)d_in[5];
    const float* sp_w2 = (const float*)d_in[6];
    const float* sp_b2 = (const float*)d_in[7];
    const float* fr_w1 = (const float*)d_in[8];
    const float* fr_b1 = (const float*)d_in[9];
    const float* fr_g = (const float*)d_in[10];
    const float* fr_be = (const float*)d_in[11];
    const float* fr_w2 = (const float*)d_in[12];
    const float* fr_b2 = (const float*)d_in[13];
    const float* ph_w1 = (const float*)d_in[14];
    const float* ph_b1 = (const float*)d_in[15];
    const float* ph_g = (const float*)d_in[16];
    const float* ph_be = (const float*)d_in[17];
    const float* ph_w2 = (const float*)d_in[18];
    const float* ph_b2 = (const float*)d_in[19];

    const int N = in_sizes[0] / 64;
    const int E = in_sizes[1] / 2;

    float* out_sp = (float*)d_out;             // [E]
    float* out_fr = out_sp + (size_t)E;        // [N,64]
    float* out_ph = out_fr + (size_t)N * 64;   // [N,128]

    // Phase 1: P/Q precompute (edge branch depends on it) — 16-node tile
    k_pq<<<(N + 15) / 16, 128>>>(x, sp_w1, sp_b1, N);

    // Phase 2: role-interleaved mega kernel
    const int nfr = (N + 31) / 32;
    const int nph = (N + 15) / 16;
    const int node_blocks = nfr + nph;
    const long ewarps = ((long)E + EPW - 1) / EPW;
    const int eblk = (int)((ewarps + 3) / 4);
    int Ga = (node_blocks + 2) / 3;
    int Gb = (eblk + 7) / 8;
    int G = Ga > Gb ? Ga : Gb;

    k_mega<<<G * 11, 128>>>(x, ei, N, E,
                            fr_w1, fr_b1, fr_g, fr_be, fr_w2, fr_b2,
                            ph_w1, ph_b1, ph_g, ph_be, ph_w2, ph_b2,
                            sp_g, sp_be, sp_w2, sp_b2,
                            out_sp, out_fr, out_ph, nfr, nph);
}

// round 17
// speedup vs baseline: 1.0581x; 1.0094x over previous
#include <cuda_runtime.h>
#include <stdint.h>
#include <math.h>

#define NMAX 50000
#define EPS_LN 1e-5f
#define EPW 16

typedef unsigned long long u64;

// Scratch: P = x @ sp_w1[0:64,:] + sp_b1, Q = x @ sp_w1[64:128,:]   (each [N,256])
__device__ float g_P[(size_t)NMAX * 256];
__device__ float g_Q[(size_t)NMAX * 256];

// ---------------- f32x2 packed helpers ----------------
__device__ __forceinline__ u64 f2pack(float lo, float hi) {
    u64 r; asm("mov.b64 %0, {%1, %2};" : "=l"(r) : "f"(lo), "f"(hi)); return r;
}
__device__ __forceinline__ void f2unpack(u64 v, float& lo, float& hi) {
    asm("mov.b64 {%0, %1}, %2;" : "=f"(lo), "=f"(hi) : "l"(v));
}
__device__ __forceinline__ u64 dup2(float v) { return f2pack(v, v); }
__device__ __forceinline__ u64 fma2(u64 a, u64 b, u64 c) {
    u64 d; asm("fma.rn.f32x2 %0, %1, %2, %3;" : "=l"(d) : "l"(a), "l"(b), "l"(c)); return d;
}
__device__ __forceinline__ u64 add2(u64 a, u64 b) {
    u64 d; asm("add.rn.f32x2 %0, %1, %2;" : "=l"(d) : "l"(a), "l"(b)); return d;
}
__device__ __forceinline__ u64 mul2(u64 a, u64 b) {
    u64 d; asm("mul.rn.f32x2 %0, %1, %2;" : "=l"(d) : "l"(a), "l"(b)); return d;
}
__device__ __forceinline__ float rcp_fast(float x) {
    float r; asm("rcp.approx.f32 %0, %1;" : "=f"(r) : "f"(x)); return r;
}
__device__ __forceinline__ float ex2_fast(float x) {
    float r; asm("ex2.approx.f32 %0, %1;" : "=f"(r) : "f"(x)); return r;
}

__device__ __forceinline__ float wredsum(float v) {
#pragma unroll
    for (int o = 16; o > 0; o >>= 1) v += __shfl_xor_sync(0xffffffffu, v, o);
    return v;
}
__device__ __forceinline__ void wredsum2(float& a, float& b) {
#pragma unroll
    for (int o = 16; o > 0; o >>= 1) {
        float ta = __shfl_xor_sync(0xffffffffu, a, o);
        float tb = __shfl_xor_sync(0xffffffffu, b, o);
        a += ta;
        b += tb;
    }
}
__device__ __forceinline__ void wredsum4(float& a, float& b, float& c, float& d) {
#pragma unroll
    for (int o = 16; o > 0; o >>= 1) {
        float ta = __shfl_xor_sync(0xffffffffu, a, o);
        float tb = __shfl_xor_sync(0xffffffffu, b, o);
        float tc = __shfl_xor_sync(0xffffffffu, c, o);
        float td = __shfl_xor_sync(0xffffffffu, d, o);
        a += ta; b += tb; c += tc; d += td;
    }
}

// fast GELU, sign-free: u*(1+erf(z)) = u + |u| - |u|*poly*e   (z = u/sqrt2)
__device__ __forceinline__ float gelu_fast(float u) {
    float z = 0.70710678118654752f * u;
    float az = fabsf(z);
    float au = fabsf(u);
    float t = rcp_fast(fmaf(0.47047f, az, 1.0f));
    float poly = t * fmaf(t, fmaf(t, 0.7478556f, -0.0958798f), 0.3480242f);
    float e = ex2_fast(-az * az * 1.4426950408889634f);
    return 0.5f * fmaf(-au * poly, e, u + au);
}

// ============================================================================
// K1: P,Q = x @ W_top (+b1), x @ W_bot.  16-node tile, 128 threads.
// ============================================================================
__global__ __launch_bounds__(128) void k_pq(const float* __restrict__ x,
                                            const float* __restrict__ w,   // [128,256]
                                            const float* __restrict__ b1,  // [256]
                                            int N) {
    __shared__ float xs[16][64];
    const int t = threadIdx.x;
    const int n0 = blockIdx.x * 16;

    {
        float4* xs4 = reinterpret_cast<float4*>(&xs[0][0]);
        const float4* x4 = reinterpret_cast<const float4*>(x);
#pragma unroll
        for (int i = t; i < 256; i += 128) {
            int node = n0 + (i >> 4);
            float4 v = make_float4(0.f, 0.f, 0.f, 0.f);
            if (node < N) v = x4[(size_t)node * 16 + (i & 15)];
            xs4[i] = v;
        }
    }
    __syncthreads();

    float aP0[16], aP1[16], aQ0[16], aQ1[16];
#pragma unroll
    for (int m = 0; m < 16; m++) { aP0[m] = 0.f; aP1[m] = 0.f; aQ0[m] = 0.f; aQ1[m] = 0.f; }

    const int c0 = t, c1 = t + 128;
#pragma unroll 2
    for (int k4 = 0; k4 < 16; k4++) {
        float wp0[4], wp1[4], wq0[4], wq1[4];
#pragma unroll
        for (int j = 0; j < 4; j++) {
            int k = k4 * 4 + j;
            wp0[j] = w[k * 256 + c0];
            wp1[j] = w[k * 256 + c1];
            wq0[j] = w[(64 + k) * 256 + c0];
            wq1[j] = w[(64 + k) * 256 + c1];
        }
#pragma unroll
        for (int m = 0; m < 16; m++) {
            float4 xv = *reinterpret_cast<const float4*>(&xs[m][k4 * 4]);
            float xa[4] = {xv.x, xv.y, xv.z, xv.w};
#pragma unroll
            for (int j = 0; j < 4; j++) {
                aP0[m] = fmaf(xa[j], wp0[j], aP0[m]);
                aP1[m] = fmaf(xa[j], wp1[j], aP1[m]);
                aQ0[m] = fmaf(xa[j], wq0[j], aQ0[m]);
                aQ1[m] = fmaf(xa[j], wq1[j], aQ1[m]);
            }
        }
    }

    const float bb0 = b1[c0], bb1 = b1[c1];
#pragma unroll
    for (int m = 0; m < 16; m++) {
        int n = n0 + m;
        if (n >= N) break;
        g_P[(size_t)n * 256 + c0] = aP0[m] + bb0;
        g_P[(size_t)n * 256 + c1] = aP1[m] + bb1;
        g_Q[(size_t)n * 256 + c0] = aQ0[m];
        g_Q[(size_t)n * 256 + c1] = aQ1[m];
    }
}

// ============================================================================
// k_edge: out = GELU(LN(P[row]+Q[col])) . w2 + b2  — dual-edge, f32x2,
// sign-free erf tail. One block = 4 warps x EPW edges.
// ============================================================================
__global__ __launch_bounds__(128, 6) void k_edge(const int* __restrict__ ei, int E,
                                                 const float* __restrict__ gm,
                                                 const float* __restrict__ bt,
                                                 const float* __restrict__ w2,
                                                 const float* __restrict__ b2p,
                                                 float* __restrict__ out) {
    const int t = threadIdx.x;
    const int lane = t & 31;
    const int wid = t >> 5;

    long e0 = ((long)blockIdx.x * 4 + wid) * EPW;
    if (e0 >= E) return;
    const int nE = (int)(E - e0 < EPW ? E - e0 : EPW);

    const float4* gmv = reinterpret_cast<const float4*>(gm);
    const float4* btv = reinterpret_cast<const float4*>(bt);
    const float4* w2v = reinterpret_cast<const float4*>(w2);
    float4 rga = gmv[lane], rgb = gmv[32 + lane];
    float4 rba = btv[lane], rbb = btv[32 + lane];
    float4 rwa = w2v[lane], rwb = w2v[32 + lane];

    const float RS2 = 0.70710678118654752f;
    u64 g2[4] = {f2pack(rga.x * RS2, rga.y * RS2), f2pack(rga.z * RS2, rga.w * RS2),
                 f2pack(rgb.x * RS2, rgb.y * RS2), f2pack(rgb.z * RS2, rgb.w * RS2)};
    u64 be2[4] = {f2pack(rba.x * RS2, rba.y * RS2), f2pack(rba.z * RS2, rba.w * RS2),
                  f2pack(rbb.x * RS2, rbb.y * RS2), f2pack(rbb.z * RS2, rbb.w * RS2)};
    u64 hw2[4] = {f2pack(rwa.x * RS2, rwa.y * RS2), f2pack(rwa.z * RS2, rwa.w * RS2),
                  f2pack(rwb.x * RS2, rwb.y * RS2), f2pack(rwb.z * RS2, rwb.w * RS2)};

    const u64 ONE2 = dup2(1.0f);
    const u64 PC = dup2(0.47047f);
    const u64 C3 = dup2(-0.7478556f);
    const u64 C2C = dup2(0.0958798f);
    const u64 C1 = dup2(-0.3480242f);
    const u64 NL2E = dup2(-1.4426950408889634f);
    const u64 AMASK = 0x7FFFFFFF7FFFFFFFull;

    const float b2 = __ldg(b2p);

    const ulonglong2* P2v = reinterpret_cast<const ulonglong2*>(g_P);
    const ulonglong2* Q2v = reinterpret_cast<const ulonglong2*>(g_Q);

    const int li = lane & 15;
    int idx = 0;
    if (li < nE) idx = ei[(lane < 16 ? e0 + li : (long)E + e0 + li)];

    for (int i = 0; i < nE; i += 2) {
        const int i2 = (i + 1 < nE) ? i + 1 : i;
        int rA = __shfl_sync(0xffffffffu, idx, i);
        int cA = __shfl_sync(0xffffffffu, idx, 16 + i);
        int rB = __shfl_sync(0xffffffffu, idx, i2);
        int cB = __shfl_sync(0xffffffffu, idx, 16 + i2);

        ulonglong2 paA = P2v[(size_t)rA * 64 + lane];
        ulonglong2 pbA = P2v[(size_t)rA * 64 + 32 + lane];
        ulonglong2 qaA = Q2v[(size_t)cA * 64 + lane];
        ulonglong2 qbA = Q2v[(size_t)cA * 64 + 32 + lane];
        ulonglong2 paB = P2v[(size_t)rB * 64 + lane];
        ulonglong2 pbB = P2v[(size_t)rB * 64 + 32 + lane];
        ulonglong2 qaB = Q2v[(size_t)cB * 64 + lane];
        ulonglong2 qbB = Q2v[(size_t)cB * 64 + 32 + lane];

        u64 sA[4], sB[4];
        sA[0] = add2(paA.x, qaA.x);
        sA[1] = add2(paA.y, qaA.y);
        sA[2] = add2(pbA.x, qbA.x);
        sA[3] = add2(pbA.y, qbA.y);
        sB[0] = add2(paB.x, qaB.x);
        sB[1] = add2(paB.y, qaB.y);
        sB[2] = add2(pbB.x, qbB.x);
        sB[3] = add2(pbB.y, qbB.y);

        u64 sumA2 = add2(add2(sA[0], sA[1]), add2(sA[2], sA[3]));
        u64 sqA2 = fma2(sA[0], sA[0], fma2(sA[1], sA[1], fma2(sA[2], sA[2], mul2(sA[3], sA[3]))));
        u64 sumB2 = add2(add2(sB[0], sB[1]), add2(sB[2], sB[3]));
        u64 sqB2 = fma2(sB[0], sB[0], fma2(sB[1], sB[1], fma2(sB[2], sB[2], mul2(sB[3], sB[3]))));

        float xl, xh;
        f2unpack(sumA2, xl, xh);
        float sumA = xl + xh;
        f2unpack(sqA2, xl, xh);
        float sqA = xl + xh;
        f2unpack(sumB2, xl, xh);
        float sumB = xl + xh;
        f2unpack(sqB2, xl, xh);
        float sqB = xl + xh;

        wredsum4(sumA, sqA, sumB, sqB);

        float meanA = sumA * (1.f / 256.f);
        float varA = sqA * (1.f / 256.f) - meanA * meanA;
        float rstdA = rsqrtf(varA + EPS_LN);
        float meanB = sumB * (1.f / 256.f);
        float varB = sqB * (1.f / 256.f) - meanB * meanB;
        float rstdB = rsqrtf(varB + EPS_LN);

        u64 A2a = dup2(rstdA), Cca = dup2(-meanA * rstdA);
        u64 A2b = dup2(rstdB), Ccb = dup2(-meanB * rstdB);

        u64 accA = 0, accB = 0;
#pragma unroll
        for (int p = 0; p < 4; p++) {
            u64 uA = fma2(sA[p], A2a, Cca);
            u64 uB = fma2(sB[p], A2b, Ccb);
            u64 zA = fma2(uA, g2[p], be2[p]);
            u64 zB = fma2(uB, g2[p], be2[p]);
            u64 azA = zA & AMASK;
            u64 azB = zB & AMASK;
            u64 dA = fma2(azA, PC, ONE2);
            u64 dB = fma2(azB, PC, ONE2);
            float dAl, dAh, dBl, dBh;
            f2unpack(dA, dAl, dAh);
            f2unpack(dB, dBl, dBh);
            u64 tA = f2pack(rcp_fast(dAl), rcp_fast(dAh));
            u64 tB = f2pack(rcp_fast(dBl), rcp_fast(dBh));
            u64 pA = fma2(tA, C3, C2C);
            u64 pB = fma2(tB, C3, C2C);
            pA = fma2(tA, pA, C1);
            pB = fma2(tB, pB, C1);
            pA = mul2(pA, tA);
            pB = mul2(pB, tB);
            u64 zzA = mul2(azA, azA);
            u64 zzB = mul2(azB, azB);
            u64 mA = mul2(zzA, NL2E);
            u64 mB = mul2(zzB, NL2E);
            float mAl, mAh, mBl, mBh;
            f2unpack(mA, mAl, mAh);
            f2unpack(mB, mBl, mBh);
            u64 eA = f2pack(ex2_fast(mAl), ex2_fast(mAh));
            u64 eB = f2pack(ex2_fast(mBl), ex2_fast(mBh));
            u64 zpazA = add2(zA, azA);
            u64 zpazB = add2(zB, azB);
            u64 wA = mul2(azA, pA);
            u64 wB = mul2(azB, pB);
            u64 termA = fma2(wA, eA, zpazA);
            u64 termB = fma2(wB, eB, zpazB);
            accA = fma2(termA, hw2[p], accA);
            accB = fma2(termB, hw2[p], accB);
        }
        float aAl, aAh, aBl, aBh;
        f2unpack(accA, aAl, aAh);
        f2unpack(accB, aBl, aBh);
        float fA = aAl + aAh, fB = aBl + aBh;
        wredsum2(fA, fB);
        if (lane == 0) {
            out[e0 + i] = fA + b2;
            if (i + 1 < nE) out[e0 + i + 1] = fB + b2;
        }
    }
}

// ============================================================================
// fr role: x[64] -> Linear(128) -> LN -> GELU -> Linear(64)
// ============================================================================
__device__ __forceinline__ void fr_role(int nb, char* smem_raw,
                                        const float* __restrict__ x,
                                        const float* __restrict__ w1,
                                        const float* __restrict__ b1,
                                        const float* __restrict__ gm,
                                        const float* __restrict__ bt,
                                        const float* __restrict__ w2,
                                        const float* __restrict__ b2,
                                        float* __restrict__ out, int N) {
    const int t = threadIdx.x;
    const int g = t >> 6;
    const int t64 = t & 63;
    float (*xs)[16] = reinterpret_cast<float (*)[16]>(smem_raw + g * 4096);   // [64][16]
    float (*hs)[128] = reinterpret_cast<float (*)[128]>(smem_raw + 8192 + g * 8192);
    const int n0 = nb * 32 + g * 16;

    {
        const float4* x4 = reinterpret_cast<const float4*>(x);
#pragma unroll
        for (int i = t64; i < 256; i += 64) {
            int node = i >> 4, kq = i & 15;
            float4 v = make_float4(0.f, 0.f, 0.f, 0.f);
            if (n0 + node < N) v = x4[(size_t)(n0 + node) * 16 + kq];
            xs[kq * 4 + 0][node] = v.x;
            xs[kq * 4 + 1][node] = v.y;
            xs[kq * 4 + 2][node] = v.z;
            xs[kq * 4 + 3][node] = v.w;
        }
    }
    __syncthreads();

    {
        u64 a0[8], a1[8];
#pragma unroll
        for (int p = 0; p < 8; p++) { a0[p] = 0; a1[p] = 0; }
        const int c0 = t64, c1 = t64 + 64;
#pragma unroll 4
        for (int k = 0; k < 64; k++) {
            u64 w0 = dup2(w1[k * 128 + c0]);
            u64 wB = dup2(w1[k * 128 + c1]);
#pragma unroll
            for (int p = 0; p < 8; p++) {
                u64 xv = *reinterpret_cast<const u64*>(&xs[k][2 * p]);
                a0[p] = fma2(xv, w0, a0[p]);
                a1[p] = fma2(xv, wB, a1[p]);
            }
        }
        float bb0 = b1[c0], bb1 = b1[c1];
#pragma unroll
        for (int p = 0; p < 8; p++) {
            float lo, hi;
            f2unpack(a0[p], lo, hi);
            hs[2 * p][c0] = lo + bb0;
            hs[2 * p + 1][c0] = hi + bb0;
            f2unpack(a1[p], lo, hi);
            hs[2 * p][c1] = lo + bb1;
            hs[2 * p + 1][c1] = hi + bb1;
        }
    }
    __syncthreads();

    {
        const int w2i = t64 >> 5, lane = t & 31;
        float4 rg4 = *reinterpret_cast<const float4*>(gm + 4 * lane);
        float4 rb4 = *reinterpret_cast<const float4*>(bt + 4 * lane);
        for (int mm = 0; mm < 8; mm++) {
            int m = w2i * 8 + mm;
            float4 v4 = *reinterpret_cast<const float4*>(&hs[m][4 * lane]);
            float sum = (v4.x + v4.y) + (v4.z + v4.w);
            float sq = fmaf(v4.x, v4.x, fmaf(v4.y, v4.y, fmaf(v4.z, v4.z, v4.w * v4.w)));
            wredsum2(sum, sq);
            float mean = sum * (1.f / 128.f);
            float var = sq * (1.f / 128.f) - mean * mean;
            float rstd = rsqrtf(var + EPS_LN);
            v4.x = gelu_fast(fmaf((v4.x - mean) * rstd, rg4.x, rb4.x));
            v4.y = gelu_fast(fmaf((v4.y - mean) * rstd, rg4.y, rb4.y));
            v4.z = gelu_fast(fmaf((v4.z - mean) * rstd, rg4.z, rb4.z));
            v4.w = gelu_fast(fmaf((v4.w - mean) * rstd, rg4.w, rb4.w));
            *reinterpret_cast<float4*>(&hs[m][4 * lane]) = v4;
        }
    }
    __syncthreads();

    {
        const int mg = t64 >> 5;
        const int o0 = (t & 31) * 2;
        float acc[8][2];
#pragma unroll
        for (int mm = 0; mm < 8; mm++) { acc[mm][0] = 0.f; acc[mm][1] = 0.f; }
#pragma unroll 2
        for (int j4 = 0; j4 < 32; j4++) {
            float2 wv[4];
#pragma unroll
            for (int j = 0; j < 4; j++)
                wv[j] = *reinterpret_cast<const float2*>(&w2[(j4 * 4 + j) * 64 + o0]);
#pragma unroll
            for (int mm = 0; mm < 8; mm++) {
                int m = mg * 8 + mm;
                float4 gv = *reinterpret_cast<const float4*>(&hs[m][j4 * 4]);
                acc[mm][0] = fmaf(gv.x, wv[0].x, acc[mm][0]);
                acc[mm][0] = fmaf(gv.y, wv[1].x, acc[mm][0]);
                acc[mm][0] = fmaf(gv.z, wv[2].x, acc[mm][0]);
                acc[mm][0] = fmaf(gv.w, wv[3].x, acc[mm][0]);
                acc[mm][1] = fmaf(gv.x, wv[0].y, acc[mm][1]);
                acc[mm][1] = fmaf(gv.y, wv[1].y, acc[mm][1]);
                acc[mm][1] = fmaf(gv.z, wv[2].y, acc[mm][1]);
                acc[mm][1] = fmaf(gv.w, wv[3].y, acc[mm][1]);
            }
        }
        float bo0 = b2[o0], bo1 = b2[o0 + 1];
#pragma unroll
        for (int mm = 0; mm < 8; mm++) {
            int n = n0 + mg * 8 + mm;
            if (n < N) {
                out[(size_t)n * 64 + o0] = acc[mm][0] + bo0;
                out[(size_t)n * 64 + o0 + 1] = acc[mm][1] + bo1;
            }
        }
    }
}

// ============================================================================
// ph role: x[64] -> Linear(256) -> LN -> GELU -> Linear(128)
// ============================================================================
__device__ __forceinline__ void ph_role(int nb, char* smem_raw,
                                        const float* __restrict__ x,
                                        const float* __restrict__ w1,
                                        const float* __restrict__ b1,
                                        const float* __restrict__ gm,
                                        const float* __restrict__ bt,
                                        const float* __restrict__ w2,
                                        const float* __restrict__ b2,
                                        float* __restrict__ out, int N) {
    const int t = threadIdx.x;
    const int g = t >> 6;
    const int t64 = t & 63;
    float (*xs)[8] = reinterpret_cast<float (*)[8]>(smem_raw + g * 2048);     // [64][8]
    float (*hs)[256] = reinterpret_cast<float (*)[256]>(smem_raw + 4096 + g * 8192);
    const int n0 = nb * 16 + g * 8;

    {
        const float4* x4 = reinterpret_cast<const float4*>(x);
#pragma unroll
        for (int i = t64; i < 128; i += 64) {
            int node = i >> 4, kq = i & 15;
            float4 v = make_float4(0.f, 0.f, 0.f, 0.f);
            if (n0 + node < N) v = x4[(size_t)(n0 + node) * 16 + kq];
            xs[kq * 4 + 0][node] = v.x;
            xs[kq * 4 + 1][node] = v.y;
            xs[kq * 4 + 2][node] = v.z;
            xs[kq * 4 + 3][node] = v.w;
        }
    }
    __syncthreads();

    {
        u64 a[4][4];
#pragma unroll
        for (int cc = 0; cc < 4; cc++)
#pragma unroll
            for (int p = 0; p < 4; p++) a[cc][p] = 0;

#pragma unroll 4
        for (int k = 0; k < 64; k++) {
            u64 wr[4];
#pragma unroll
            for (int cc = 0; cc < 4; cc++)
                wr[cc] = dup2(w1[k * 256 + t64 + 64 * cc]);
#pragma unroll
            for (int p = 0; p < 4; p++) {
                u64 xv = *reinterpret_cast<const u64*>(&xs[k][2 * p]);
#pragma unroll
                for (int cc = 0; cc < 4; cc++) a[cc][p] = fma2(xv, wr[cc], a[cc][p]);
            }
        }
#pragma unroll
        for (int cc = 0; cc < 4; cc++) {
            float bb = b1[t64 + 64 * cc];
#pragma unroll
            for (int p = 0; p < 4; p++) {
                float lo, hi;
                f2unpack(a[cc][p], lo, hi);
                hs[2 * p][t64 + 64 * cc] = lo + bb;
                hs[2 * p + 1][t64 + 64 * cc] = hi + bb;
            }
        }
    }
    __syncthreads();

    {
        const int w2i = t64 >> 5, lane = t & 31;
        float4 rg4a = *reinterpret_cast<const float4*>(gm + 8 * lane);
        float4 rg4b = *reinterpret_cast<const float4*>(gm + 8 * lane + 4);
        float4 rb4a = *reinterpret_cast<const float4*>(bt + 8 * lane);
        float4 rb4b = *reinterpret_cast<const float4*>(bt + 8 * lane + 4);
        for (int mm = 0; mm < 4; mm++) {
            int m = w2i * 4 + mm;
            float4 va = *reinterpret_cast<const float4*>(&hs[m][8 * lane]);
            float4 vb = *reinterpret_cast<const float4*>(&hs[m][8 * lane + 4]);
            float sum = ((va.x + va.y) + (va.z + va.w)) + ((vb.x + vb.y) + (vb.z + vb.w));
            float sq = fmaf(va.x, va.x, fmaf(va.y, va.y, fmaf(va.z, va.z, va.w * va.w)));
            sq = fmaf(vb.x, vb.x, fmaf(vb.y, vb.y, fmaf(vb.z, vb.z, fmaf(vb.w, vb.w, sq))));
            wredsum2(sum, sq);
            float mean = sum * (1.f / 256.f);
            float var = sq * (1.f / 256.f) - mean * mean;
            float rstd = rsqrtf(var + EPS_LN);
            va.x = gelu_fast(fmaf((va.x - mean) * rstd, rg4a.x, rb4a.x));
            va.y = gelu_fast(fmaf((va.y - mean) * rstd, rg4a.y, rb4a.y));
            va.z = gelu_fast(fmaf((va.z - mean) * rstd, rg4a.z, rb4a.z));
            va.w = gelu_fast(fmaf((va.w - mean) * rstd, rg4a.w, rb4a.w));
            vb.x = gelu_fast(fmaf((vb.x - mean) * rstd, rg4b.x, rb4b.x));
            vb.y = gelu_fast(fmaf((vb.y - mean) * rstd, rg4b.y, rb4b.y));
            vb.z = gelu_fast(fmaf((vb.z - mean) * rstd, rg4b.z, rb4b.z));
            vb.w = gelu_fast(fmaf((vb.w - mean) * rstd, rg4b.w, rb4b.w));
            *reinterpret_cast<float4*>(&hs[m][8 * lane]) = va;
            *reinterpret_cast<float4*>(&hs[m][8 * lane + 4]) = vb;
        }
    }
    __syncthreads();

    {
        const int mg = t64 >> 5;
        const int o0 = (t & 31) * 4;
        float acc[4][4];
#pragma unroll
        for (int mm = 0; mm < 4; mm++)
#pragma unroll
            for (int oo = 0; oo < 4; oo++) acc[mm][oo] = 0.f;

#pragma unroll 2
        for (int j4 = 0; j4 < 64; j4++) {
            float4 wv[4];
#pragma unroll
            for (int j = 0; j < 4; j++)
                wv[j] = *reinterpret_cast<const float4*>(&w2[(j4 * 4 + j) * 128 + o0]);
#pragma unroll
            for (int mm = 0; mm < 4; mm++) {
                int m = mg * 4 + mm;
                float4 gv = *reinterpret_cast<const float4*>(&hs[m][j4 * 4]);
                float gvals[4] = {gv.x, gv.y, gv.z, gv.w};
#pragma unroll
                for (int j = 0; j < 4; j++) {
                    acc[mm][0] = fmaf(gvals[j], wv[j].x, acc[mm][0]);
                    acc[mm][1] = fmaf(gvals[j], wv[j].y, acc[mm][1]);
                    acc[mm][2] = fmaf(gvals[j], wv[j].z, acc[mm][2]);
                    acc[mm][3] = fmaf(gvals[j], wv[j].w, acc[mm][3]);
                }
            }
        }
        float4 bo = *reinterpret_cast<const float4*>(&b2[o0]);
#pragma unroll
        for (int mm = 0; mm < 4; mm++) {
            int n = n0 + mg * 4 + mm;
            if (n < N) {
                float4 rr;
                rr.x = acc[mm][0] + bo.x;
                rr.y = acc[mm][1] + bo.y;
                rr.z = acc[mm][2] + bo.z;
                rr.w = acc[mm][3] + bo.w;
                *reinterpret_cast<float4*>(&out[(size_t)n * 128 + o0]) = rr;
            }
        }
    }
}

// ============================================================================
// k_nodes: fr blocks then ph blocks (no edge role)
// ============================================================================
__global__ __launch_bounds__(128, 6) void k_nodes(
    const float* __restrict__ x, int N,
    const float* __restrict__ fr_w1, const float* __restrict__ fr_b1,
    const float* __restrict__ fr_g, const float* __restrict__ fr_be,
    const float* __restrict__ fr_w2, const float* __restrict__ fr_b2,
    const float* __restrict__ ph_w1, const float* __restrict__ ph_b1,
    const float* __restrict__ ph_g, const float* __restrict__ ph_be,
    const float* __restrict__ ph_w2, const float* __restrict__ ph_b2,
    float* __restrict__ out_fr, float* __restrict__ out_ph, int nfr) {
    __shared__ __align__(16) char smem_raw[24576];
    const int b = blockIdx.x;
    if (b < nfr) {
        fr_role(b, smem_raw, x, fr_w1, fr_b1, fr_g, fr_be, fr_w2, fr_b2, out_fr, N);
    } else {
        ph_role(b - nfr, smem_raw, x, ph_w1, ph_b1, ph_g, ph_be, ph_w2, ph_b2, out_ph, N);
    }
}

// ============================================================================
// launch — graph-forked: stream0: pq -> edge ; stream2: nodes (concurrent)
// ============================================================================
extern "C" void kernel_launch(void* const* d_in, const int* in_sizes, int n_in,
                              void* d_out, int out_size) {
    const float* x = (const float*)d_in[0];
    const int* ei = (const int*)d_in[1];
    const float* sp_w1 = (const float*)d_in[2];
    const float* sp_b1 = (const float*)d_in[3];
    const float* sp_g = (const float*)d_in[4];
    const float* sp_be = (const float*)d_in[5];
    const float* sp_w2 = (const float*)d_in[6];
    const float* sp_b2 = (const float*)d_in[7];
    const float* fr_w1 = (const float*)d_in[8];
    const float* fr_b1 = (const float*)d_in[9];
    const float* fr_g = (const float*)d_in[10];
    const float* fr_be = (const float*)d_in[11];
    const float* fr_w2 = (const float*)d_in[12];
    const float* fr_b2 = (const float*)d_in[13];
    const float* ph_w1 = (const float*)d_in[14];
    const float* ph_b1 = (const float*)d_in[15];
    const float* ph_g = (const float*)d_in[16];
    const float* ph_be = (const float*)d_in[17];
    const float* ph_w2 = (const float*)d_in[18];
    const float* ph_b2 = (const float*)d_in[19];

    const int N = in_sizes[0] / 64;
    const int E = in_sizes[1] / 2;

    float* out_sp = (float*)d_out;             // [E]
    float* out_fr = out_sp + (size_t)E;        // [N,64]
    float* out_ph = out_fr + (size_t)N * 64;   // [N,128]

    const int npq = (N + 15) / 16;
    const int nfr = (N + 31) / 32;
    const int nph = (N + 15) / 16;
    const long ewarps = ((long)E + EPW - 1) / EPW;
    const int eblk = (int)((ewarps + 3) / 4);

    // Fork a side stream for the node kernel (capture-safe event pattern).
    // Handles are intentionally NOT destroyed: kernel_launch runs only for the
    // correctness call + capture call; destroying inside an active capture is
    // illegal, and leaking 2-3 host handles is harmless & deterministic.
    cudaStream_t s2;
    cudaStreamCreateWithFlags(&s2, cudaStreamNonBlocking);
    cudaEvent_t eFork, eJoin;
    cudaEventCreateWithFlags(&eFork, cudaEventDisableTiming);
    cudaEventCreateWithFlags(&eJoin, cudaEventDisableTiming);

    cudaEventRecord(eFork, 0);
    cudaStreamWaitEvent(s2, eFork, 0);

    // stream2: node branch (independent of P/Q)
    k_nodes<<<nfr + nph, 128, 0, s2>>>(x, N,
                                       fr_w1, fr_b1, fr_g, fr_be, fr_w2, fr_b2,
                                       ph_w1, ph_b1, ph_g, ph_be, ph_w2, ph_b2,
                                       out_fr, out_ph, nfr);
    cudaEventRecord(eJoin, s2);

    // stream0: pq -> edge (true dependency)
    k_pq<<<npq, 128>>>(x, sp_w1, sp_b1, N);
    k_edge<<<eblk, 128>>>(ei, E, sp_g, sp_be, sp_w2, sp_b2, out_sp);

    // join so the graph leaf is ordered after both branches
    cudaStreamWaitEvent(0, eJoin, 0);
}